// round 8
// baseline (speedup 1.0000x reference)
#include <cuda_runtime.h>
#include <math.h>

#define BB 16
#define NN 4096
#define SS 1024
#define KK 32
#define NTOT (BB*SS*KK)   /* 524288 positions */

typedef unsigned long long ull;

// ---- packed f32x2 helpers (Blackwell FFMA2 path) ---------------------------
__device__ __forceinline__ ull pack2(float lo, float hi) {
    ull r; asm("mov.b64 %0, {%1, %2};" : "=l"(r) : "f"(lo), "f"(hi)); return r;
}
__device__ __forceinline__ void unpack2(ull v, float& lo, float& hi) {
    asm("mov.b64 {%0, %1}, %2;" : "=f"(lo), "=f"(hi) : "l"(v));
}
__device__ __forceinline__ ull fma2(ull a, ull b, ull c) {
    ull d; asm("fma.rn.f32x2 %0, %1, %2, %3;" : "=l"(d) : "l"(a), "l"(b), "l"(c)); return d;
}
__device__ __forceinline__ ull add2(ull a, ull b) {
    ull d; asm("add.rn.f32x2 %0, %1, %2;" : "=l"(d) : "l"(a), "l"(b)); return d;
}
__device__ __forceinline__ ull mul2(ull a, ull b) {
    ull d; asm("mul.rn.f32x2 %0, %1, %2;" : "=l"(d) : "l"(a), "l"(b)); return d;
}

// ---------------- scratch (static device globals) ---------------------------
__device__ float d_grouped[(size_t)NTOT*6];          // 12.6 MB
__device__ float d_y[(size_t)NTOT*64];               // 134 MB (y1, then in-place y2)
__device__ float d_mx[(size_t)BB*SS*128];            // 8 MB
__device__ float d_mn[(size_t)BB*SS*128];            // 8 MB
__device__ float d_ps1[64*4096],  d_pq1[64*4096];
__device__ float d_ps2[64*4096],  d_pq2[64*4096];
__device__ float d_ps3[128*8192], d_pq3[128*8192];
__device__ float d_nmean[3][128];
__device__ float d_nscale[3][128];
__device__ float d_nbeta[3][128];
__device__ int   d_pad[8];

// ---------------- pad: 3 launches so k_fps sits at my 0-based index 3 -------
// (captured launch across R1/R2/R3/R5/R7 was always MY index 3)
__global__ void k_pad(int i) { if (threadIdx.x == 0) d_pad[i] = i; }

// ---------------- FPS: one block/batch, 256 thr, 16 pts/thr -----------------
// Identical to the R7 passing kernel (measurement target this round).
__global__ void __launch_bounds__(256,1) k_fps(const float* __restrict__ xyz,
                                               float* __restrict__ out) {
    int b = blockIdx.x;
    int tid = threadIdx.x;
    int lane = tid & 31, wid = tid >> 5;
    const float* X = xyz + (size_t)b * NN * 3;
    __shared__ ull skey[2][8];
    ull px2[8], py2[8], pz2[8];
    float dd[16];
    int i0 = tid * 16;
    #pragma unroll
    for (int i = 0; i < 8; i++) {
        int j0 = i0 + 2*i, j1 = i0 + 2*i + 1;
        px2[i] = pack2(X[j0*3+0], X[j1*3+0]);
        py2[i] = pack2(X[j0*3+1], X[j1*3+1]);
        pz2[i] = pack2(X[j0*3+2], X[j1*3+2]);
    }
    #pragma unroll
    for (int j = 0; j < 16; j++) dd[j] = 1e10f;
    int w = 0;

    for (int it = 0; it < SS; it++) {
        float cx = __ldg(X + w * 3 + 0);
        float cy = __ldg(X + w * 3 + 1);
        float cz = __ldg(X + w * 3 + 2);
        if (tid == 0) {
            float* o = out + ((size_t)b * SS + it) * 3;
            o[0] = cx; o[1] = cy; o[2] = cz;
        }
        if (it == SS - 1) break;

        ull ncx = pack2(-cx, -cx), ncy = pack2(-cy, -cy), ncz = pack2(-cz, -cz);
        #pragma unroll
        for (int i = 0; i < 8; i++) {
            ull dx = add2(px2[i], ncx);          // px - cx (IEEE identical)
            ull dy = add2(py2[i], ncy);
            ull dz = add2(pz2[i], ncz);
            ull t  = mul2(dx, dx);
            t = fma2(dy, dy, t);
            t = fma2(dz, dz, t);
            float d0, d1; unpack2(t, d0, d1);
            dd[2*i]   = fminf(dd[2*i],   d0);
            dd[2*i+1] = fminf(dd[2*i+1], d1);
        }
        float m[8];
        #pragma unroll
        for (int i = 0; i < 8; i++) m[i] = fmaxf(dd[2*i], dd[2*i+1]);
        float m0 = fmaxf(fmaxf(m[0], m[1]), fmaxf(m[2], m[3]));
        float m1 = fmaxf(fmaxf(m[4], m[5]), fmaxf(m[6], m[7]));
        float bv = fmaxf(m0, m1);
        int li = 0;
        #pragma unroll
        for (int j = 15; j >= 0; j--) if (dd[j] == bv) li = i0 + j;
        float wv = bv;
        #pragma unroll
        for (int off = 16; off; off >>= 1)
            wv = fmaxf(wv, __shfl_xor_sync(0xffffffffu, wv, off));
        unsigned msk = __ballot_sync(0xffffffffu, bv == wv);
        int src = __ffs(msk) - 1;
        int wli = __shfl_sync(0xffffffffu, li, src);
        ull key = ((ull)__float_as_uint(wv) << 32) | (unsigned)(0xFFFF - wli);
        if (lane == 0) skey[it & 1][wid] = key;
        __syncthreads();
        const ull* sk = skey[it & 1];
        ull a0 = sk[0] > sk[1] ? sk[0] : sk[1];
        ull a1 = sk[2] > sk[3] ? sk[2] : sk[3];
        ull a2 = sk[4] > sk[5] ? sk[4] : sk[5];
        ull a3 = sk[6] > sk[7] ? sk[6] : sk[7];
        ull b0 = a0 > a1 ? a0 : a1;
        ull b1 = a2 > a3 ? a2 : a3;
        ull k0 = b0 > b1 ? b0 : b1;
        w = 0xFFFF - (int)(k0 & 0xFFFFFFFFull);
    }
}

// ---------------- ball query + grouping: one warp per centroid --------------
__global__ void k_group(const float* __restrict__ xyz,
                        const float* __restrict__ pts,
                        const float* __restrict__ nxyz) {
    int gw = (blockIdx.x * blockDim.x + threadIdx.x) >> 5;
    int lane = threadIdx.x & 31;
    if (gw >= BB * SS) return;
    int b = gw >> 10;
    const float* X = xyz + (size_t)b * NN * 3;
    const float* P = pts + (size_t)b * NN * 3;
    const float* c = nxyz + (size_t)gw * 3;
    float cx = c[0], cy = c[1], cz = c[2];
    float s2 = cx*cx + cy*cy + cz*cz;
    float* G = d_grouped + (size_t)gw * KK * 6;

    int count = 0, firstIdx = 0;
    bool haveFirst = false;
    for (int c4 = 0; c4 < NN / 128 && count < KK; c4++) {
        #pragma unroll
        for (int s = 0; s < 4; s++) {
            int pi = (c4 * 4 + s) * 32 + lane;
            float x = X[pi*3], y = X[pi*3+1], z = X[pi*3+2];
            float d2 = x*x + y*y + z*z;
            float dt = cx*x + cy*y + cz*z;
            float sq = (s2 + d2) - 2.0f * dt;
            bool inside = !(sq > 0.04f);
            unsigned m = __ballot_sync(0xffffffffu, inside);
            if (!haveFirst && m) { firstIdx = (c4*4+s)*32 + (__ffs(m) - 1); haveFirst = true; }
            int slot = count + __popc(m & ((1u << lane) - 1u));
            if (inside && slot < KK) {
                float* g = G + slot * 6;
                g[0] = x - cx; g[1] = y - cy; g[2] = z - cz;
                g[3] = P[pi*3]; g[4] = P[pi*3+1]; g[5] = P[pi*3+2];
            }
            count += __popc(m);
        }
    }
    if (count < KK) {
        int fi = firstIdx;
        float x = X[fi*3], y = X[fi*3+1], z = X[fi*3+2];
        float p0 = P[fi*3], p1 = P[fi*3+1], p2 = P[fi*3+2];
        for (int slot = count + lane; slot < KK; slot += 32) {
            float* g = G + slot * 6;
            g[0] = x - cx; g[1] = y - cy; g[2] = z - cz;
            g[3] = p0; g[4] = p1; g[5] = p2;
        }
    }
}

// ---------------- layer 1: 6 -> 64 ------------------------------------------
__global__ void k_layer1(const float* __restrict__ W, const float* __restrict__ Bv) {
    __shared__ __align__(16) float sin_[128 * 6];
    __shared__ float rs[256], rq[256];
    size_t pos0 = (size_t)blockIdx.x * 128;
    int tid = threadIdx.x;
    if (tid < 192) {
        float4 v = ((const float4*)(d_grouped + pos0 * 6))[tid];
        ((float4*)sin_)[tid] = v;
    }
    int c = tid & 63, g = tid >> 6;
    float w[6];
    #pragma unroll
    for (int i = 0; i < 6; i++) w[i] = W[c * 6 + i];
    float bb = Bv[c];
    __syncthreads();
    float ls = 0.f, lq = 0.f;
    for (int p = g; p < 128; p += 4) {
        float acc = bb;
        #pragma unroll
        for (int i = 0; i < 6; i++) acc += w[i] * sin_[p * 6 + i];
        d_y[(pos0 + p) * 64 + c] = acc;
        ls += acc; lq += acc * acc;
    }
    rs[tid] = ls; rq[tid] = lq;
    __syncthreads();
    if (tid < 64) {
        float S = rs[tid] + rs[tid+64] + rs[tid+128] + rs[tid+192];
        float Q = rq[tid] + rq[tid+64] + rq[tid+128] + rq[tid+192];
        d_ps1[tid * 4096 + blockIdx.x] = S;
        d_pq1[tid * 4096 + blockIdx.x] = Q;
    }
}

// ---------------- finalize: reduce partials, build norm params ---------------
__global__ void k_finalize(int layer, int nblk,
                           const float* __restrict__ gamma,
                           const float* __restrict__ beta) {
    const float* ps = layer == 0 ? d_ps1 : layer == 1 ? d_ps2 : d_ps3;
    const float* pq = layer == 0 ? d_pq1 : layer == 1 ? d_pq2 : d_pq3;
    int c = blockIdx.x;
    __shared__ double sd[256], sq[256];
    double s = 0.0, q = 0.0;
    const float4* ps4 = (const float4*)(ps + (size_t)c * nblk);
    const float4* pq4 = (const float4*)(pq + (size_t)c * nblk);
    for (int i = threadIdx.x; i < nblk / 4; i += 256) {
        float4 a = ps4[i], bq = pq4[i];
        s += (double)a.x + a.y + a.z + a.w;
        q += (double)bq.x + bq.y + bq.z + bq.w;
    }
    sd[threadIdx.x] = s; sq[threadIdx.x] = q;
    __syncthreads();
    for (int off = 128; off; off >>= 1) {
        if (threadIdx.x < off) {
            sd[threadIdx.x] += sd[threadIdx.x + off];
            sq[threadIdx.x] += sq[threadIdx.x + off];
        }
        __syncthreads();
    }
    if (threadIdx.x == 0) {
        double n = (double)NTOT;
        double mean = sd[0] / n;
        double var  = sq[0] / n - mean * mean;
        float rstd = rsqrtf((float)var + 1e-5f);
        d_nmean[layer][c]  = (float)mean;
        d_nscale[layer][c] = gamma[c] * rstd;
        d_nbeta[layer][c]  = beta[c];
    }
}

// ---------------- layer 2: 64 -> 64, FFMA2, pair-interleaved shared ---------
__global__ void __launch_bounds__(256,1) k_layer2(const float* __restrict__ W,
                                                  const float* __restrict__ Bv) {
    __shared__ __align__(16) float s[64 * 128];   // 32KB
    __shared__ float rs[256], rq[256];
    size_t pos0 = (size_t)blockIdx.x * 128;
    int tid = threadIdx.x;
    {
        int cin0 = (tid & 15) * 4;
        float nm0 = d_nmean[0][cin0],   sc0 = d_nscale[0][cin0],   nb0 = d_nbeta[0][cin0];
        float nm1 = d_nmean[0][cin0+1], sc1 = d_nscale[0][cin0+1], nb1 = d_nbeta[0][cin0+1];
        float nm2 = d_nmean[0][cin0+2], sc2 = d_nscale[0][cin0+2], nb2 = d_nbeta[0][cin0+2];
        float nm3 = d_nmean[0][cin0+3], sc3 = d_nscale[0][cin0+3], nb3 = d_nbeta[0][cin0+3];
        const float4* src = (const float4*)(d_y + pos0 * 64);
        for (int t4 = tid; t4 < 2048; t4 += 256) {
            float4 v = src[t4];
            int p = t4 >> 4;
            float* dst = s + (p >> 1) * 128 + (p & 1) + cin0 * 2;
            dst[0] = fmaxf((v.x - nm0) * sc0 + nb0, 0.f);
            dst[2] = fmaxf((v.y - nm1) * sc1 + nb1, 0.f);
            dst[4] = fmaxf((v.z - nm2) * sc2 + nb2, 0.f);
            dst[6] = fmaxf((v.w - nm3) * sc3 + nb3, 0.f);
        }
    }
    int c = tid & 63, g = tid >> 6;
    ull w2[64];
    #pragma unroll
    for (int i = 0; i < 64; i++) { float wv = W[c * 64 + i]; w2[i] = pack2(wv, wv); }
    float bb = Bv[c];
    __syncthreads();
    float ls = 0.f, lq = 0.f;
    for (int q = g; q < 64; q += 4) {
        const ulonglong2* sp = (const ulonglong2*)(s + q * 128);
        ull acc_a = pack2(bb, bb), acc_b = pack2(0.f, 0.f);
        #pragma unroll
        for (int i = 0; i < 32; i++) {
            ulonglong2 v = sp[i];
            acc_a = fma2(w2[2*i],   v.x, acc_a);
            acc_b = fma2(w2[2*i+1], v.y, acc_b);
        }
        ull acc = add2(acc_a, acc_b);
        float lo, hi; unpack2(acc, lo, hi);
        d_y[(pos0 + 2*q)     * 64 + c] = lo;
        d_y[(pos0 + 2*q + 1) * 64 + c] = hi;
        ls += lo + hi; lq += lo*lo + hi*hi;
    }
    rs[tid] = ls; rq[tid] = lq;
    __syncthreads();
    if (tid < 64) {
        float S = rs[tid] + rs[tid+64] + rs[tid+128] + rs[tid+192];
        float Q = rq[tid] + rq[tid+64] + rq[tid+128] + rq[tid+192];
        d_ps2[tid * 4096 + blockIdx.x] = S;
        d_pq2[tid * 4096 + blockIdx.x] = Q;
    }
}

// ---------------- layer 3: 64 -> 128, FFMA2, fused max/min pool --------------
__global__ void __launch_bounds__(256,1) k_layer3(const float* __restrict__ W,
                                                  const float* __restrict__ Bv) {
    __shared__ __align__(16) float s[32 * 128];   // 16KB
    __shared__ float rs[256], rq[256];
    __shared__ float smx[2][2][128], smn[2][2][128];
    size_t pos0 = (size_t)blockIdx.x * 64;        // 2 centroids per block
    int tid = threadIdx.x;
    {
        int cin0 = (tid & 15) * 4;
        float nm0 = d_nmean[1][cin0],   sc0 = d_nscale[1][cin0],   nb0 = d_nbeta[1][cin0];
        float nm1 = d_nmean[1][cin0+1], sc1 = d_nscale[1][cin0+1], nb1 = d_nbeta[1][cin0+1];
        float nm2 = d_nmean[1][cin0+2], sc2 = d_nscale[1][cin0+2], nb2 = d_nbeta[1][cin0+2];
        float nm3 = d_nmean[1][cin0+3], sc3 = d_nscale[1][cin0+3], nb3 = d_nbeta[1][cin0+3];
        const float4* src = (const float4*)(d_y + pos0 * 64);
        for (int t4 = tid; t4 < 1024; t4 += 256) {
            float4 v = src[t4];
            int p = t4 >> 4;
            float* dst = s + (p >> 1) * 128 + (p & 1) + cin0 * 2;
            dst[0] = fmaxf((v.x - nm0) * sc0 + nb0, 0.f);
            dst[2] = fmaxf((v.y - nm1) * sc1 + nb1, 0.f);
            dst[4] = fmaxf((v.z - nm2) * sc2 + nb2, 0.f);
            dst[6] = fmaxf((v.w - nm3) * sc3 + nb3, 0.f);
        }
    }
    int c = tid & 127, g = tid >> 7;
    ull w2[64];
    #pragma unroll
    for (int i = 0; i < 64; i++) { float wv = W[c * 64 + i]; w2[i] = pack2(wv, wv); }
    float bb = Bv[c];
    __syncthreads();
    float ls = 0.f, lq = 0.f;
    float mx0 = -INFINITY, mn0 = INFINITY, mx1 = -INFINITY, mn1 = INFINITY;
    for (int q = g; q < 32; q += 2) {
        const ulonglong2* sp = (const ulonglong2*)(s + q * 128);
        ull acc_a = pack2(bb, bb), acc_b = pack2(0.f, 0.f);
        #pragma unroll
        for (int i = 0; i < 32; i++) {
            ulonglong2 v = sp[i];
            acc_a = fma2(w2[2*i],   v.x, acc_a);
            acc_b = fma2(w2[2*i+1], v.y, acc_b);
        }
        ull acc = add2(acc_a, acc_b);
        float lo, hi; unpack2(acc, lo, hi);
        ls += lo + hi; lq += lo*lo + hi*hi;
        float M = fmaxf(lo, hi), m = fminf(lo, hi);
        if (q < 16) { mx0 = fmaxf(mx0, M); mn0 = fminf(mn0, m); }
        else        { mx1 = fmaxf(mx1, M); mn1 = fminf(mn1, m); }
    }
    smx[g][0][c] = mx0; smx[g][1][c] = mx1;
    smn[g][0][c] = mn0; smn[g][1][c] = mn1;
    rs[tid] = ls; rq[tid] = lq;
    __syncthreads();
    {
        int cent = tid >> 7, cc = tid & 127;
        float M = fmaxf(smx[0][cent][cc], smx[1][cent][cc]);
        float m = fminf(smn[0][cent][cc], smn[1][cent][cc]);
        size_t o = (size_t)(blockIdx.x * 2 + cent) * 128 + cc;
        d_mx[o] = M; d_mn[o] = m;
    }
    if (tid < 128) {
        float S = rs[tid] + rs[tid + 128];
        float Q = rq[tid] + rq[tid + 128];
        d_ps3[tid * 8192 + blockIdx.x] = S;
        d_pq3[tid * 8192 + blockIdx.x] = Q;
    }
}

// ---------------- final pool: norm(max-or-min) + relu, write output ----------
__global__ void k_poolf(float* __restrict__ out) {
    int g = blockIdx.x * 256 + threadIdx.x;
    int c = g & 127;
    float scv = d_nscale[2][c];
    float v = (scv >= 0.f) ? d_mx[g] : d_mn[g];
    out[(size_t)BB * SS * 3 + g] = fmaxf((v - d_nmean[2][c]) * scv + d_nbeta[2][c], 0.f);
}

// ---------------- launch -----------------------------------------------------
extern "C" void kernel_launch(void* const* d_in, const int* in_sizes, int n_in,
                              void* d_out, int out_size) {
    const float* xyz = (const float*)d_in[0];
    const float* pts = (const float*)d_in[1];
    const float* w0  = (const float*)d_in[2];
    const float* b0  = (const float*)d_in[3];
    const float* g0  = (const float*)d_in[4];
    const float* be0 = (const float*)d_in[5];
    const float* w1  = (const float*)d_in[6];
    const float* b1  = (const float*)d_in[7];
    const float* g1  = (const float*)d_in[8];
    const float* be1 = (const float*)d_in[9];
    const float* w2  = (const float*)d_in[10];
    const float* b2  = (const float*)d_in[11];
    const float* g2  = (const float*)d_in[12];
    const float* be2 = (const float*)d_in[13];
    float* out = (float*)d_out;

    // 3 pads: k_fps becomes my 0-based launch index 3 -> the profiled launch
    k_pad<<<1, 32>>>(0);
    k_pad<<<1, 32>>>(1);
    k_pad<<<1, 32>>>(2);
    k_fps<<<BB, 256>>>(xyz, out);
    k_group<<<(BB * SS) / 8, 256>>>(xyz, pts, out);
    k_layer1<<<NTOT / 128, 256>>>(w0, b0);
    k_finalize<<<64, 256>>>(0, 4096, g0, be0);
    k_layer2<<<NTOT / 128, 256>>>(w1, b1);
    k_finalize<<<64, 256>>>(1, 4096, g1, be1);
    k_layer3<<<NTOT / 64, 256>>>(w2, b2);
    k_finalize<<<128, 256>>>(2, 8192, g2, be2);
    k_poolf<<<(BB * SS * 128) / 256, 256>>>(out);
}

// round 9
// speedup vs baseline: 1.6687x; 1.6687x over previous
#include <cuda_runtime.h>
#include <math.h>

#define BB 16
#define NN 4096
#define SS 1024
#define KK 32
#define NTOT (BB*SS*KK)   /* 524288 positions */

typedef unsigned long long ull;

// ---- packed f32x2 helpers ---------------------------------------------------
__device__ __forceinline__ ull pack2(float lo, float hi) {
    ull r; asm("mov.b64 %0, {%1, %2};" : "=l"(r) : "f"(lo), "f"(hi)); return r;
}
__device__ __forceinline__ void unpack2(ull v, float& lo, float& hi) {
    asm("mov.b64 {%0, %1}, %2;" : "=f"(lo), "=f"(hi) : "l"(v));
}
__device__ __forceinline__ ull fma2(ull a, ull b, ull c) {
    ull d; asm("fma.rn.f32x2 %0, %1, %2, %3;" : "=l"(d) : "l"(a), "l"(b), "l"(c)); return d;
}
__device__ __forceinline__ ull add2(ull a, ull b) {
    ull d; asm("add.rn.f32x2 %0, %1, %2;" : "=l"(d) : "l"(a), "l"(b)); return d;
}
__device__ __forceinline__ ull mul2(ull a, ull b) {
    ull d; asm("mul.rn.f32x2 %0, %1, %2;" : "=l"(d) : "l"(a), "l"(b)); return d;
}

// ---------------- scratch (static device globals) ---------------------------
__device__ float d_grouped[(size_t)NTOT*6];
__device__ float d_y[(size_t)NTOT*64];
__device__ float d_mx[(size_t)BB*SS*128];
__device__ float d_mn[(size_t)BB*SS*128];
__device__ float d_ps1[64*4096],  d_pq1[64*4096];
__device__ float d_ps2[64*4096],  d_pq2[64*4096];
__device__ float d_ps3[128*8192], d_pq3[128*8192];
__device__ float d_nmean[3][128];
__device__ float d_nscale[3][128];
__device__ float d_nbeta[3][128];
__device__ float d_wt1[64*64];     // w1 transposed: [i][c] (c fastest)
__device__ float d_wt2[64*128];    // w2 transposed: [i][c]
__device__ int   d_pad[8];

__global__ void k_pad(int i) { if (threadIdx.x == 0) d_pad[i] = i; }

// ---------------- prep: transpose weights so layer loads are coalesced ------
__global__ void k_prep(const float* __restrict__ w1, const float* __restrict__ w2) {
    int t = blockIdx.x * 256 + threadIdx.x;
    if (t < 64 * 64)  { int c = t >> 6, i = t & 63; d_wt1[i * 64 + c]  = w1[t]; }
    if (t < 128 * 64) { int c = t >> 6, i = t & 63; d_wt2[i * 128 + c] = w2[t]; }
}

// ---------------- FPS: identical to R8 passing kernel (458us measured) ------
__global__ void __launch_bounds__(256,1) k_fps(const float* __restrict__ xyz,
                                               float* __restrict__ out) {
    int b = blockIdx.x;
    int tid = threadIdx.x;
    int lane = tid & 31, wid = tid >> 5;
    const float* X = xyz + (size_t)b * NN * 3;
    __shared__ ull skey[2][8];
    ull px2[8], py2[8], pz2[8];
    float dd[16];
    int i0 = tid * 16;
    #pragma unroll
    for (int i = 0; i < 8; i++) {
        int j0 = i0 + 2*i, j1 = i0 + 2*i + 1;
        px2[i] = pack2(X[j0*3+0], X[j1*3+0]);
        py2[i] = pack2(X[j0*3+1], X[j1*3+1]);
        pz2[i] = pack2(X[j0*3+2], X[j1*3+2]);
    }
    #pragma unroll
    for (int j = 0; j < 16; j++) dd[j] = 1e10f;
    int w = 0;

    for (int it = 0; it < SS; it++) {
        float cx = __ldg(X + w * 3 + 0);
        float cy = __ldg(X + w * 3 + 1);
        float cz = __ldg(X + w * 3 + 2);
        if (tid == 0) {
            float* o = out + ((size_t)b * SS + it) * 3;
            o[0] = cx; o[1] = cy; o[2] = cz;
        }
        if (it == SS - 1) break;

        ull ncx = pack2(-cx, -cx), ncy = pack2(-cy, -cy), ncz = pack2(-cz, -cz);
        #pragma unroll
        for (int i = 0; i < 8; i++) {
            ull dx = add2(px2[i], ncx);
            ull dy = add2(py2[i], ncy);
            ull dz = add2(pz2[i], ncz);
            ull t  = mul2(dx, dx);
            t = fma2(dy, dy, t);
            t = fma2(dz, dz, t);
            float d0, d1; unpack2(t, d0, d1);
            dd[2*i]   = fminf(dd[2*i],   d0);
            dd[2*i+1] = fminf(dd[2*i+1], d1);
        }
        float m[8];
        #pragma unroll
        for (int i = 0; i < 8; i++) m[i] = fmaxf(dd[2*i], dd[2*i+1]);
        float m0 = fmaxf(fmaxf(m[0], m[1]), fmaxf(m[2], m[3]));
        float m1 = fmaxf(fmaxf(m[4], m[5]), fmaxf(m[6], m[7]));
        float bv = fmaxf(m0, m1);
        int li = 0;
        #pragma unroll
        for (int j = 15; j >= 0; j--) if (dd[j] == bv) li = i0 + j;
        float wv = bv;
        #pragma unroll
        for (int off = 16; off; off >>= 1)
            wv = fmaxf(wv, __shfl_xor_sync(0xffffffffu, wv, off));
        unsigned msk = __ballot_sync(0xffffffffu, bv == wv);
        int src = __ffs(msk) - 1;
        int wli = __shfl_sync(0xffffffffu, li, src);
        ull key = ((ull)__float_as_uint(wv) << 32) | (unsigned)(0xFFFF - wli);
        if (lane == 0) skey[it & 1][wid] = key;
        __syncthreads();
        const ull* sk = skey[it & 1];
        ull a0 = sk[0] > sk[1] ? sk[0] : sk[1];
        ull a1 = sk[2] > sk[3] ? sk[2] : sk[3];
        ull a2 = sk[4] > sk[5] ? sk[4] : sk[5];
        ull a3 = sk[6] > sk[7] ? sk[6] : sk[7];
        ull b0 = a0 > a1 ? a0 : a1;
        ull b1 = a2 > a3 ? a2 : a3;
        ull k0 = b0 > b1 ? b0 : b1;
        w = 0xFFFF - (int)(k0 & 0xFFFFFFFFull);
    }
}

// ---------------- ball query + grouping (profiled this round) ---------------
__global__ void k_group(const float* __restrict__ xyz,
                        const float* __restrict__ pts,
                        const float* __restrict__ nxyz) {
    int gw = (blockIdx.x * blockDim.x + threadIdx.x) >> 5;
    int lane = threadIdx.x & 31;
    if (gw >= BB * SS) return;
    int b = gw >> 10;
    const float* X = xyz + (size_t)b * NN * 3;
    const float* P = pts + (size_t)b * NN * 3;
    const float* c = nxyz + (size_t)gw * 3;
    float cx = c[0], cy = c[1], cz = c[2];
    float s2 = cx*cx + cy*cy + cz*cz;
    float* G = d_grouped + (size_t)gw * KK * 6;

    int count = 0, firstIdx = 0;
    bool haveFirst = false;
    for (int c4 = 0; c4 < NN / 128 && count < KK; c4++) {
        #pragma unroll
        for (int s = 0; s < 4; s++) {
            int pi = (c4 * 4 + s) * 32 + lane;
            float x = X[pi*3], y = X[pi*3+1], z = X[pi*3+2];
            float d2 = x*x + y*y + z*z;
            float dt = cx*x + cy*y + cz*z;
            float sq = (s2 + d2) - 2.0f * dt;
            bool inside = !(sq > 0.04f);
            unsigned m = __ballot_sync(0xffffffffu, inside);
            if (!haveFirst && m) { firstIdx = (c4*4+s)*32 + (__ffs(m) - 1); haveFirst = true; }
            int slot = count + __popc(m & ((1u << lane) - 1u));
            if (inside && slot < KK) {
                float* g = G + slot * 6;
                g[0] = x - cx; g[1] = y - cy; g[2] = z - cz;
                g[3] = P[pi*3]; g[4] = P[pi*3+1]; g[5] = P[pi*3+2];
            }
            count += __popc(m);
        }
    }
    if (count < KK) {
        int fi = firstIdx;
        float x = X[fi*3], y = X[fi*3+1], z = X[fi*3+2];
        float p0 = P[fi*3], p1 = P[fi*3+1], p2 = P[fi*3+2];
        for (int slot = count + lane; slot < KK; slot += 32) {
            float* g = G + slot * 6;
            g[0] = x - cx; g[1] = y - cy; g[2] = z - cz;
            g[3] = p0; g[4] = p1; g[5] = p2;
        }
    }
}

// ---------------- layer 1: 6 -> 64 ------------------------------------------
__global__ void k_layer1(const float* __restrict__ W, const float* __restrict__ Bv) {
    __shared__ __align__(16) float sin_[128 * 6];
    __shared__ float rs[256], rq[256];
    size_t pos0 = (size_t)blockIdx.x * 128;
    int tid = threadIdx.x;
    if (tid < 192) {
        float4 v = ((const float4*)(d_grouped + pos0 * 6))[tid];
        ((float4*)sin_)[tid] = v;
    }
    int c = tid & 63, g = tid >> 6;
    float w[6];
    #pragma unroll
    for (int i = 0; i < 6; i++) w[i] = W[c * 6 + i];
    float bb = Bv[c];
    __syncthreads();
    float ls = 0.f, lq = 0.f;
    for (int p = g; p < 128; p += 4) {
        float acc = bb;
        #pragma unroll
        for (int i = 0; i < 6; i++) acc += w[i] * sin_[p * 6 + i];
        d_y[(pos0 + p) * 64 + c] = acc;
        ls += acc; lq += acc * acc;
    }
    rs[tid] = ls; rq[tid] = lq;
    __syncthreads();
    if (tid < 64) {
        float S = rs[tid] + rs[tid+64] + rs[tid+128] + rs[tid+192];
        float Q = rq[tid] + rq[tid+64] + rq[tid+128] + rq[tid+192];
        d_ps1[tid * 4096 + blockIdx.x] = S;
        d_pq1[tid * 4096 + blockIdx.x] = Q;
    }
}

// ---------------- finalize --------------------------------------------------
__global__ void k_finalize(int layer, int nblk,
                           const float* __restrict__ gamma,
                           const float* __restrict__ beta) {
    const float* ps = layer == 0 ? d_ps1 : layer == 1 ? d_ps2 : d_ps3;
    const float* pq = layer == 0 ? d_pq1 : layer == 1 ? d_pq2 : d_pq3;
    int c = blockIdx.x;
    __shared__ double sd[256], sq[256];
    double s = 0.0, q = 0.0;
    const float4* ps4 = (const float4*)(ps + (size_t)c * nblk);
    const float4* pq4 = (const float4*)(pq + (size_t)c * nblk);
    for (int i = threadIdx.x; i < nblk / 4; i += 256) {
        float4 a = ps4[i], bq = pq4[i];
        s += (double)a.x + a.y + a.z + a.w;
        q += (double)bq.x + bq.y + bq.z + bq.w;
    }
    sd[threadIdx.x] = s; sq[threadIdx.x] = q;
    __syncthreads();
    for (int off = 128; off; off >>= 1) {
        if (threadIdx.x < off) {
            sd[threadIdx.x] += sd[threadIdx.x + off];
            sq[threadIdx.x] += sq[threadIdx.x + off];
        }
        __syncthreads();
    }
    if (threadIdx.x == 0) {
        double n = (double)NTOT;
        double mean = sd[0] / n;
        double var  = sq[0] / n - mean * mean;
        float rstd = rsqrtf((float)var + 1e-5f);
        d_nmean[layer][c]  = (float)mean;
        d_nscale[layer][c] = gamma[c] * rstd;
        d_nbeta[layer][c]  = beta[c];
    }
}

// ---------------- layer 2: 64 -> 64, coalesced transposed weight load -------
__global__ void __launch_bounds__(256,1) k_layer2(const float* __restrict__ Bv) {
    __shared__ __align__(16) float s[64 * 128];
    __shared__ float rs[256], rq[256];
    size_t pos0 = (size_t)blockIdx.x * 128;
    int tid = threadIdx.x;
    {
        int cin0 = (tid & 15) * 4;
        float nm0 = d_nmean[0][cin0],   sc0 = d_nscale[0][cin0],   nb0 = d_nbeta[0][cin0];
        float nm1 = d_nmean[0][cin0+1], sc1 = d_nscale[0][cin0+1], nb1 = d_nbeta[0][cin0+1];
        float nm2 = d_nmean[0][cin0+2], sc2 = d_nscale[0][cin0+2], nb2 = d_nbeta[0][cin0+2];
        float nm3 = d_nmean[0][cin0+3], sc3 = d_nscale[0][cin0+3], nb3 = d_nbeta[0][cin0+3];
        const float4* src = (const float4*)(d_y + pos0 * 64);
        for (int t4 = tid; t4 < 2048; t4 += 256) {
            float4 v = src[t4];
            int p = t4 >> 4;
            float* dst = s + (p >> 1) * 128 + (p & 1) + cin0 * 2;
            dst[0] = fmaxf((v.x - nm0) * sc0 + nb0, 0.f);
            dst[2] = fmaxf((v.y - nm1) * sc1 + nb1, 0.f);
            dst[4] = fmaxf((v.z - nm2) * sc2 + nb2, 0.f);
            dst[6] = fmaxf((v.w - nm3) * sc3 + nb3, 0.f);
        }
    }
    int c = tid & 63, g = tid >> 6;
    ull w2[64];
    #pragma unroll
    for (int i = 0; i < 64; i++) { float wv = d_wt1[i * 64 + c]; w2[i] = pack2(wv, wv); }
    float bb = Bv[c];
    __syncthreads();
    float ls = 0.f, lq = 0.f;
    for (int q = g; q < 64; q += 4) {
        const ulonglong2* sp = (const ulonglong2*)(s + q * 128);
        ull acc_a = pack2(bb, bb), acc_b = pack2(0.f, 0.f);
        #pragma unroll
        for (int i = 0; i < 32; i++) {
            ulonglong2 v = sp[i];
            acc_a = fma2(w2[2*i],   v.x, acc_a);
            acc_b = fma2(w2[2*i+1], v.y, acc_b);
        }
        ull acc = add2(acc_a, acc_b);
        float lo, hi; unpack2(acc, lo, hi);
        d_y[(pos0 + 2*q)     * 64 + c] = lo;
        d_y[(pos0 + 2*q + 1) * 64 + c] = hi;
        ls += lo + hi; lq += lo*lo + hi*hi;
    }
    rs[tid] = ls; rq[tid] = lq;
    __syncthreads();
    if (tid < 64) {
        float S = rs[tid] + rs[tid+64] + rs[tid+128] + rs[tid+192];
        float Q = rq[tid] + rq[tid+64] + rq[tid+128] + rq[tid+192];
        d_ps2[tid * 4096 + blockIdx.x] = S;
        d_pq2[tid * 4096 + blockIdx.x] = Q;
    }
}

// ---------------- layer 3: 64 -> 128, coalesced weights, fused pool ---------
__global__ void __launch_bounds__(256,1) k_layer3(const float* __restrict__ Bv) {
    __shared__ __align__(16) float s[32 * 128];
    __shared__ float rs[256], rq[256];
    __shared__ float smx[2][2][128], smn[2][2][128];
    size_t pos0 = (size_t)blockIdx.x * 64;
    int tid = threadIdx.x;
    {
        int cin0 = (tid & 15) * 4;
        float nm0 = d_nmean[1][cin0],   sc0 = d_nscale[1][cin0],   nb0 = d_nbeta[1][cin0];
        float nm1 = d_nmean[1][cin0+1], sc1 = d_nscale[1][cin0+1], nb1 = d_nbeta[1][cin0+1];
        float nm2 = d_nmean[1][cin0+2], sc2 = d_nscale[1][cin0+2], nb2 = d_nbeta[1][cin0+2];
        float nm3 = d_nmean[1][cin0+3], sc3 = d_nscale[1][cin0+3], nb3 = d_nbeta[1][cin0+3];
        const float4* src = (const float4*)(d_y + pos0 * 64);
        for (int t4 = tid; t4 < 1024; t4 += 256) {
            float4 v = src[t4];
            int p = t4 >> 4;
            float* dst = s + (p >> 1) * 128 + (p & 1) + cin0 * 2;
            dst[0] = fmaxf((v.x - nm0) * sc0 + nb0, 0.f);
            dst[2] = fmaxf((v.y - nm1) * sc1 + nb1, 0.f);
            dst[4] = fmaxf((v.z - nm2) * sc2 + nb2, 0.f);
            dst[6] = fmaxf((v.w - nm3) * sc3 + nb3, 0.f);
        }
    }
    int c = tid & 127, g = tid >> 7;
    ull w2[64];
    #pragma unroll
    for (int i = 0; i < 64; i++) { float wv = d_wt2[i * 128 + c]; w2[i] = pack2(wv, wv); }
    float bb = Bv[c];
    __syncthreads();
    float ls = 0.f, lq = 0.f;
    float mx0 = -INFINITY, mn0 = INFINITY, mx1 = -INFINITY, mn1 = INFINITY;
    for (int q = g; q < 32; q += 2) {
        const ulonglong2* sp = (const ulonglong2*)(s + q * 128);
        ull acc_a = pack2(bb, bb), acc_b = pack2(0.f, 0.f);
        #pragma unroll
        for (int i = 0; i < 32; i++) {
            ulonglong2 v = sp[i];
            acc_a = fma2(w2[2*i],   v.x, acc_a);
            acc_b = fma2(w2[2*i+1], v.y, acc_b);
        }
        ull acc = add2(acc_a, acc_b);
        float lo, hi; unpack2(acc, lo, hi);
        ls += lo + hi; lq += lo*lo + hi*hi;
        float M = fmaxf(lo, hi), m = fminf(lo, hi);
        if (q < 16) { mx0 = fmaxf(mx0, M); mn0 = fminf(mn0, m); }
        else        { mx1 = fmaxf(mx1, M); mn1 = fminf(mn1, m); }
    }
    smx[g][0][c] = mx0; smx[g][1][c] = mx1;
    smn[g][0][c] = mn0; smn[g][1][c] = mn1;
    rs[tid] = ls; rq[tid] = lq;
    __syncthreads();
    {
        int cent = tid >> 7, cc = tid & 127;
        float M = fmaxf(smx[0][cent][cc], smx[1][cent][cc]);
        float m = fminf(smn[0][cent][cc], smn[1][cent][cc]);
        size_t o = (size_t)(blockIdx.x * 2 + cent) * 128 + cc;
        d_mx[o] = M; d_mn[o] = m;
    }
    if (tid < 128) {
        float S = rs[tid] + rs[tid + 128];
        float Q = rq[tid] + rq[tid + 128];
        d_ps3[tid * 8192 + blockIdx.x] = S;
        d_pq3[tid * 8192 + blockIdx.x] = Q;
    }
}

// ---------------- final pool -------------------------------------------------
__global__ void k_poolf(float* __restrict__ out) {
    int g = blockIdx.x * 256 + threadIdx.x;
    int c = g & 127;
    float scv = d_nscale[2][c];
    float v = (scv >= 0.f) ? d_mx[g] : d_mn[g];
    out[(size_t)BB * SS * 3 + g] = fmaxf((v - d_nmean[2][c]) * scv + d_nbeta[2][c], 0.f);
}

// ---------------- launch -----------------------------------------------------
extern "C" void kernel_launch(void* const* d_in, const int* in_sizes, int n_in,
                              void* d_out, int out_size) {
    const float* xyz = (const float*)d_in[0];
    const float* pts = (const float*)d_in[1];
    const float* w0  = (const float*)d_in[2];
    const float* b0  = (const float*)d_in[3];
    const float* g0  = (const float*)d_in[4];
    const float* be0 = (const float*)d_in[5];
    const float* w1  = (const float*)d_in[6];
    const float* b1  = (const float*)d_in[7];
    const float* g1  = (const float*)d_in[8];
    const float* be1 = (const float*)d_in[9];
    const float* w2  = (const float*)d_in[10];
    const float* b2  = (const float*)d_in[11];
    const float* g2  = (const float*)d_in[12];
    const float* be2 = (const float*)d_in[13];
    float* out = (float*)d_out;

    k_prep<<<32, 256>>>(w1, w2);                 // idx 0
    k_fps<<<BB, 256>>>(xyz, out);                // idx 1
    k_pad<<<1, 32>>>(0);                         // idx 2
    k_group<<<(BB * SS) / 8, 256>>>(xyz, pts, out);  // idx 3 -> profiled
    k_layer1<<<NTOT / 128, 256>>>(w0, b0);
    k_finalize<<<64, 256>>>(0, 4096, g0, be0);
    k_layer2<<<NTOT / 128, 256>>>(b1);
    k_finalize<<<64, 256>>>(1, 4096, g1, be1);
    k_layer3<<<NTOT / 64, 256>>>(b2);
    k_finalize<<<128, 256>>>(2, 8192, g2, be2);
    k_poolf<<<(BB * SS * 128) / 256, 256>>>(out);
}

// round 10
// speedup vs baseline: 1.7593x; 1.0543x over previous
#include <cuda_runtime.h>
#include <math.h>

#define BB 16
#define NN 4096
#define SS 1024
#define KK 32
#define NTOT (BB*SS*KK)   /* 524288 positions */

typedef unsigned long long ull;

// ---- packed f32x2 helpers ---------------------------------------------------
__device__ __forceinline__ ull pack2(float lo, float hi) {
    ull r; asm("mov.b64 %0, {%1, %2};" : "=l"(r) : "f"(lo), "f"(hi)); return r;
}
__device__ __forceinline__ void unpack2(ull v, float& lo, float& hi) {
    asm("mov.b64 {%0, %1}, %2;" : "=f"(lo), "=f"(hi) : "l"(v));
}
__device__ __forceinline__ ull fma2(ull a, ull b, ull c) {
    ull d; asm("fma.rn.f32x2 %0, %1, %2, %3;" : "=l"(d) : "l"(a), "l"(b), "l"(c)); return d;
}
__device__ __forceinline__ ull add2(ull a, ull b) {
    ull d; asm("add.rn.f32x2 %0, %1, %2;" : "=l"(d) : "l"(a), "l"(b)); return d;
}
__device__ __forceinline__ ull mul2(ull a, ull b) {
    ull d; asm("mul.rn.f32x2 %0, %1, %2;" : "=l"(d) : "l"(a), "l"(b)); return d;
}
// warp max of a non-negative float via integer redux (bit order == float order
// for values >= 0). redux.sync.max.u32 is sm_80+, valid at compute_100.
__device__ __forceinline__ float warp_max_nonneg(float v) {
    unsigned r;
    asm("redux.sync.max.u32 %0, %1, 0xffffffff;" : "=r"(r) : "r"(__float_as_uint(v)));
    return __uint_as_float(r);
}

// ---------------- scratch (static device globals) ---------------------------
__device__ float d_grouped[(size_t)NTOT*6];
__device__ float d_y[(size_t)NTOT*64];
__device__ float d_mx[(size_t)BB*SS*128];
__device__ float d_mn[(size_t)BB*SS*128];
__device__ float d_ps1[64*4096],  d_pq1[64*4096];
__device__ float d_ps2[64*4096],  d_pq2[64*4096];
__device__ float d_ps3[128*8192], d_pq3[128*8192];
__device__ float d_nmean[3][128];
__device__ float d_nscale[3][128];
__device__ float d_nbeta[3][128];
__device__ float d_wt1[64*64];     // w1 transposed: [i][c] (c fastest)
__device__ float d_wt2[64*128];    // w2 transposed: [i][c]

// ---------------- prep: transpose weights so layer loads are coalesced ------
__global__ void k_prep(const float* __restrict__ w1, const float* __restrict__ w2) {
    int t = blockIdx.x * 256 + threadIdx.x;
    if (t < 64 * 64)  { int c = t >> 6, i = t & 63; d_wt1[i * 64 + c]  = w1[t]; }
    if (t < 128 * 64) { int c = t >> 6, i = t & 63; d_wt2[i * 128 + c] = w2[t]; }
}

// ---------------- FPS: one block/batch; redux-based warp reduce -------------
__global__ void __launch_bounds__(256,1) k_fps(const float* __restrict__ xyz,
                                               float* __restrict__ out) {
    int b = blockIdx.x;
    int tid = threadIdx.x;
    int lane = tid & 31, wid = tid >> 5;
    const float* X = xyz + (size_t)b * NN * 3;
    __shared__ ull skey[2][8];
    ull px2[8], py2[8], pz2[8];
    float dd[16];
    int i0 = tid * 16;
    #pragma unroll
    for (int i = 0; i < 8; i++) {
        int j0 = i0 + 2*i, j1 = i0 + 2*i + 1;
        px2[i] = pack2(X[j0*3+0], X[j1*3+0]);
        py2[i] = pack2(X[j0*3+1], X[j1*3+1]);
        pz2[i] = pack2(X[j0*3+2], X[j1*3+2]);
    }
    #pragma unroll
    for (int j = 0; j < 16; j++) dd[j] = 1e10f;
    int w = 0;

    for (int it = 0; it < SS; it++) {
        float cx = __ldg(X + w * 3 + 0);
        float cy = __ldg(X + w * 3 + 1);
        float cz = __ldg(X + w * 3 + 2);
        if (tid == 0) {
            float* o = out + ((size_t)b * SS + it) * 3;
            o[0] = cx; o[1] = cy; o[2] = cz;
        }
        if (it == SS - 1) break;

        ull ncx = pack2(-cx, -cx), ncy = pack2(-cy, -cy), ncz = pack2(-cz, -cz);
        #pragma unroll
        for (int i = 0; i < 8; i++) {
            ull dx = add2(px2[i], ncx);          // px - cx (IEEE identical)
            ull dy = add2(py2[i], ncy);
            ull dz = add2(pz2[i], ncz);
            ull t  = mul2(dx, dx);
            t = fma2(dy, dy, t);
            t = fma2(dz, dz, t);
            float d0, d1; unpack2(t, d0, d1);
            dd[2*i]   = fminf(dd[2*i],   d0);
            dd[2*i+1] = fminf(dd[2*i+1], d1);
        }
        float m[8];
        #pragma unroll
        for (int i = 0; i < 8; i++) m[i] = fmaxf(dd[2*i], dd[2*i+1]);
        float m0 = fmaxf(fmaxf(m[0], m[1]), fmaxf(m[2], m[3]));
        float m1 = fmaxf(fmaxf(m[4], m[5]), fmaxf(m[6], m[7]));
        float bv = fmaxf(m0, m1);
        int li = 0;
        #pragma unroll
        for (int j = 15; j >= 0; j--) if (dd[j] == bv) li = i0 + j;
        // single-instruction warp max (bit-identical to fmaxf chain: dd >= 0)
        float wv = warp_max_nonneg(bv);
        unsigned msk = __ballot_sync(0xffffffffu, bv == wv);
        int src = __ffs(msk) - 1;                // lowest lane = lowest index
        int wli = __shfl_sync(0xffffffffu, li, src);
        ull key = ((ull)__float_as_uint(wv) << 32) | (unsigned)(0xFFFF - wli);
        if (lane == 0) skey[it & 1][wid] = key;
        __syncthreads();
        const ull* sk = skey[it & 1];
        ull a0 = sk[0] > sk[1] ? sk[0] : sk[1];
        ull a1 = sk[2] > sk[3] ? sk[2] : sk[3];
        ull a2 = sk[4] > sk[5] ? sk[4] : sk[5];
        ull a3 = sk[6] > sk[7] ? sk[6] : sk[7];
        ull b0 = a0 > a1 ? a0 : a1;
        ull b1 = a2 > a3 ? a2 : a3;
        ull k0 = b0 > b1 ? b0 : b1;
        w = 0xFFFF - (int)(k0 & 0xFFFFFFFFull);
    }
}

// ---------------- ball query + grouping (75us measured) ---------------------
__global__ void k_group(const float* __restrict__ xyz,
                        const float* __restrict__ pts,
                        const float* __restrict__ nxyz) {
    int gw = (blockIdx.x * blockDim.x + threadIdx.x) >> 5;
    int lane = threadIdx.x & 31;
    if (gw >= BB * SS) return;
    int b = gw >> 10;
    const float* X = xyz + (size_t)b * NN * 3;
    const float* P = pts + (size_t)b * NN * 3;
    const float* c = nxyz + (size_t)gw * 3;
    float cx = c[0], cy = c[1], cz = c[2];
    float s2 = cx*cx + cy*cy + cz*cz;
    float* G = d_grouped + (size_t)gw * KK * 6;

    int count = 0, firstIdx = 0;
    bool haveFirst = false;
    for (int c4 = 0; c4 < NN / 128 && count < KK; c4++) {
        #pragma unroll
        for (int s = 0; s < 4; s++) {
            int pi = (c4 * 4 + s) * 32 + lane;
            float x = X[pi*3], y = X[pi*3+1], z = X[pi*3+2];
            float d2 = x*x + y*y + z*z;
            float dt = cx*x + cy*y + cz*z;
            float sq = (s2 + d2) - 2.0f * dt;
            bool inside = !(sq > 0.04f);
            unsigned m = __ballot_sync(0xffffffffu, inside);
            if (!haveFirst && m) { firstIdx = (c4*4+s)*32 + (__ffs(m) - 1); haveFirst = true; }
            int slot = count + __popc(m & ((1u << lane) - 1u));
            if (inside && slot < KK) {
                float* g = G + slot * 6;
                g[0] = x - cx; g[1] = y - cy; g[2] = z - cz;
                g[3] = P[pi*3]; g[4] = P[pi*3+1]; g[5] = P[pi*3+2];
            }
            count += __popc(m);
        }
    }
    if (count < KK) {
        int fi = firstIdx;
        float x = X[fi*3], y = X[fi*3+1], z = X[fi*3+2];
        float p0 = P[fi*3], p1 = P[fi*3+1], p2 = P[fi*3+2];
        for (int slot = count + lane; slot < KK; slot += 32) {
            float* g = G + slot * 6;
            g[0] = x - cx; g[1] = y - cy; g[2] = z - cz;
            g[3] = p0; g[4] = p1; g[5] = p2;
        }
    }
}

// ---------------- layer 1: 6 -> 64 (profiled this round) --------------------
__global__ void k_layer1(const float* __restrict__ W, const float* __restrict__ Bv) {
    __shared__ __align__(16) float sin_[128 * 6];
    __shared__ float rs[256], rq[256];
    size_t pos0 = (size_t)blockIdx.x * 128;
    int tid = threadIdx.x;
    if (tid < 192) {
        float4 v = ((const float4*)(d_grouped + pos0 * 6))[tid];
        ((float4*)sin_)[tid] = v;
    }
    int c = tid & 63, g = tid >> 6;
    float w[6];
    #pragma unroll
    for (int i = 0; i < 6; i++) w[i] = W[c * 6 + i];
    float bb = Bv[c];
    __syncthreads();
    float ls = 0.f, lq = 0.f;
    for (int p = g; p < 128; p += 4) {
        float acc = bb;
        #pragma unroll
        for (int i = 0; i < 6; i++) acc += w[i] * sin_[p * 6 + i];
        d_y[(pos0 + p) * 64 + c] = acc;
        ls += acc; lq += acc * acc;
    }
    rs[tid] = ls; rq[tid] = lq;
    __syncthreads();
    if (tid < 64) {
        float S = rs[tid] + rs[tid+64] + rs[tid+128] + rs[tid+192];
        float Q = rq[tid] + rq[tid+64] + rq[tid+128] + rq[tid+192];
        d_ps1[tid * 4096 + blockIdx.x] = S;
        d_pq1[tid * 4096 + blockIdx.x] = Q;
    }
}

// ---------------- finalize --------------------------------------------------
__global__ void k_finalize(int layer, int nblk,
                           const float* __restrict__ gamma,
                           const float* __restrict__ beta) {
    const float* ps = layer == 0 ? d_ps1 : layer == 1 ? d_ps2 : d_ps3;
    const float* pq = layer == 0 ? d_pq1 : layer == 1 ? d_pq2 : d_pq3;
    int c = blockIdx.x;
    __shared__ double sd[256], sq[256];
    double s = 0.0, q = 0.0;
    const float4* ps4 = (const float4*)(ps + (size_t)c * nblk);
    const float4* pq4 = (const float4*)(pq + (size_t)c * nblk);
    for (int i = threadIdx.x; i < nblk / 4; i += 256) {
        float4 a = ps4[i], bq = pq4[i];
        s += (double)a.x + a.y + a.z + a.w;
        q += (double)bq.x + bq.y + bq.z + bq.w;
    }
    sd[threadIdx.x] = s; sq[threadIdx.x] = q;
    __syncthreads();
    for (int off = 128; off; off >>= 1) {
        if (threadIdx.x < off) {
            sd[threadIdx.x] += sd[threadIdx.x + off];
            sq[threadIdx.x] += sq[threadIdx.x + off];
        }
        __syncthreads();
    }
    if (threadIdx.x == 0) {
        double n = (double)NTOT;
        double mean = sd[0] / n;
        double var  = sq[0] / n - mean * mean;
        float rstd = rsqrtf((float)var + 1e-5f);
        d_nmean[layer][c]  = (float)mean;
        d_nscale[layer][c] = gamma[c] * rstd;
        d_nbeta[layer][c]  = beta[c];
    }
}

// ---------------- layer 2: 64 -> 64, coalesced transposed weight load -------
__global__ void __launch_bounds__(256,1) k_layer2(const float* __restrict__ Bv) {
    __shared__ __align__(16) float s[64 * 128];
    __shared__ float rs[256], rq[256];
    size_t pos0 = (size_t)blockIdx.x * 128;
    int tid = threadIdx.x;
    {
        int cin0 = (tid & 15) * 4;
        float nm0 = d_nmean[0][cin0],   sc0 = d_nscale[0][cin0],   nb0 = d_nbeta[0][cin0];
        float nm1 = d_nmean[0][cin0+1], sc1 = d_nscale[0][cin0+1], nb1 = d_nbeta[0][cin0+1];
        float nm2 = d_nmean[0][cin0+2], sc2 = d_nscale[0][cin0+2], nb2 = d_nbeta[0][cin0+2];
        float nm3 = d_nmean[0][cin0+3], sc3 = d_nscale[0][cin0+3], nb3 = d_nbeta[0][cin0+3];
        const float4* src = (const float4*)(d_y + pos0 * 64);
        for (int t4 = tid; t4 < 2048; t4 += 256) {
            float4 v = src[t4];
            int p = t4 >> 4;
            float* dst = s + (p >> 1) * 128 + (p & 1) + cin0 * 2;
            dst[0] = fmaxf((v.x - nm0) * sc0 + nb0, 0.f);
            dst[2] = fmaxf((v.y - nm1) * sc1 + nb1, 0.f);
            dst[4] = fmaxf((v.z - nm2) * sc2 + nb2, 0.f);
            dst[6] = fmaxf((v.w - nm3) * sc3 + nb3, 0.f);
        }
    }
    int c = tid & 63, g = tid >> 6;
    ull w2[64];
    #pragma unroll
    for (int i = 0; i < 64; i++) { float wv = d_wt1[i * 64 + c]; w2[i] = pack2(wv, wv); }
    float bb = Bv[c];
    __syncthreads();
    float ls = 0.f, lq = 0.f;
    for (int q = g; q < 64; q += 4) {
        const ulonglong2* sp = (const ulonglong2*)(s + q * 128);
        ull acc_a = pack2(bb, bb), acc_b = pack2(0.f, 0.f);
        #pragma unroll
        for (int i = 0; i < 32; i++) {
            ulonglong2 v = sp[i];
            acc_a = fma2(w2[2*i],   v.x, acc_a);
            acc_b = fma2(w2[2*i+1], v.y, acc_b);
        }
        ull acc = add2(acc_a, acc_b);
        float lo, hi; unpack2(acc, lo, hi);
        d_y[(pos0 + 2*q)     * 64 + c] = lo;
        d_y[(pos0 + 2*q + 1) * 64 + c] = hi;
        ls += lo + hi; lq += lo*lo + hi*hi;
    }
    rs[tid] = ls; rq[tid] = lq;
    __syncthreads();
    if (tid < 64) {
        float S = rs[tid] + rs[tid+64] + rs[tid+128] + rs[tid+192];
        float Q = rq[tid] + rq[tid+64] + rq[tid+128] + rq[tid+192];
        d_ps2[tid * 4096 + blockIdx.x] = S;
        d_pq2[tid * 4096 + blockIdx.x] = Q;
    }
}

// ---------------- layer 3: 64 -> 128, coalesced weights, fused pool ---------
__global__ void __launch_bounds__(256,1) k_layer3(const float* __restrict__ Bv) {
    __shared__ __align__(16) float s[32 * 128];
    __shared__ float rs[256], rq[256];
    __shared__ float smx[2][2][128], smn[2][2][128];
    size_t pos0 = (size_t)blockIdx.x * 64;
    int tid = threadIdx.x;
    {
        int cin0 = (tid & 15) * 4;
        float nm0 = d_nmean[1][cin0],   sc0 = d_nscale[1][cin0],   nb0 = d_nbeta[1][cin0];
        float nm1 = d_nmean[1][cin0+1], sc1 = d_nscale[1][cin0+1], nb1 = d_nbeta[1][cin0+1];
        float nm2 = d_nmean[1][cin0+2], sc2 = d_nscale[1][cin0+2], nb2 = d_nbeta[1][cin0+2];
        float nm3 = d_nmean[1][cin0+3], sc3 = d_nscale[1][cin0+3], nb3 = d_nbeta[1][cin0+3];
        const float4* src = (const float4*)(d_y + pos0 * 64);
        for (int t4 = tid; t4 < 1024; t4 += 256) {
            float4 v = src[t4];
            int p = t4 >> 4;
            float* dst = s + (p >> 1) * 128 + (p & 1) + cin0 * 2;
            dst[0] = fmaxf((v.x - nm0) * sc0 + nb0, 0.f);
            dst[2] = fmaxf((v.y - nm1) * sc1 + nb1, 0.f);
            dst[4] = fmaxf((v.z - nm2) * sc2 + nb2, 0.f);
            dst[6] = fmaxf((v.w - nm3) * sc3 + nb3, 0.f);
        }
    }
    int c = tid & 127, g = tid >> 7;
    ull w2[64];
    #pragma unroll
    for (int i = 0; i < 64; i++) { float wv = d_wt2[i * 128 + c]; w2[i] = pack2(wv, wv); }
    float bb = Bv[c];
    __syncthreads();
    float ls = 0.f, lq = 0.f;
    float mx0 = -INFINITY, mn0 = INFINITY, mx1 = -INFINITY, mn1 = INFINITY;
    for (int q = g; q < 32; q += 2) {
        const ulonglong2* sp = (const ulonglong2*)(s + q * 128);
        ull acc_a = pack2(bb, bb), acc_b = pack2(0.f, 0.f);
        #pragma unroll
        for (int i = 0; i < 32; i++) {
            ulonglong2 v = sp[i];
            acc_a = fma2(w2[2*i],   v.x, acc_a);
            acc_b = fma2(w2[2*i+1], v.y, acc_b);
        }
        ull acc = add2(acc_a, acc_b);
        float lo, hi; unpack2(acc, lo, hi);
        ls += lo + hi; lq += lo*lo + hi*hi;
        float M = fmaxf(lo, hi), m = fminf(lo, hi);
        if (q < 16) { mx0 = fmaxf(mx0, M); mn0 = fminf(mn0, m); }
        else        { mx1 = fmaxf(mx1, M); mn1 = fminf(mn1, m); }
    }
    smx[g][0][c] = mx0; smx[g][1][c] = mx1;
    smn[g][0][c] = mn0; smn[g][1][c] = mn1;
    rs[tid] = ls; rq[tid] = lq;
    __syncthreads();
    {
        int cent = tid >> 7, cc = tid & 127;
        float M = fmaxf(smx[0][cent][cc], smx[1][cent][cc]);
        float m = fminf(smn[0][cent][cc], smn[1][cent][cc]);
        size_t o = (size_t)(blockIdx.x * 2 + cent) * 128 + cc;
        d_mx[o] = M; d_mn[o] = m;
    }
    if (tid < 128) {
        float S = rs[tid] + rs[tid + 128];
        float Q = rq[tid] + rq[tid + 128];
        d_ps3[tid * 8192 + blockIdx.x] = S;
        d_pq3[tid * 8192 + blockIdx.x] = Q;
    }
}

// ---------------- final pool -------------------------------------------------
__global__ void k_poolf(float* __restrict__ out) {
    int g = blockIdx.x * 256 + threadIdx.x;
    int c = g & 127;
    float scv = d_nscale[2][c];
    float v = (scv >= 0.f) ? d_mx[g] : d_mn[g];
    out[(size_t)BB * SS * 3 + g] = fmaxf((v - d_nmean[2][c]) * scv + d_nbeta[2][c], 0.f);
}

// ---------------- launch -----------------------------------------------------
extern "C" void kernel_launch(void* const* d_in, const int* in_sizes, int n_in,
                              void* d_out, int out_size) {
    const float* xyz = (const float*)d_in[0];
    const float* pts = (const float*)d_in[1];
    const float* w0  = (const float*)d_in[2];
    const float* b0  = (const float*)d_in[3];
    const float* g0  = (const float*)d_in[4];
    const float* be0 = (const float*)d_in[5];
    const float* w1  = (const float*)d_in[6];
    const float* b1  = (const float*)d_in[7];
    const float* g1  = (const float*)d_in[8];
    const float* be1 = (const float*)d_in[9];
    const float* w2  = (const float*)d_in[10];
    const float* b2  = (const float*)d_in[11];
    const float* g2  = (const float*)d_in[12];
    const float* be2 = (const float*)d_in[13];
    float* out = (float*)d_out;

    k_prep<<<32, 256>>>(w1, w2);                      // idx 0
    k_fps<<<BB, 256>>>(xyz, out);                     // idx 1
    k_group<<<(BB * SS) / 8, 256>>>(xyz, pts, out);   // idx 2
    k_layer1<<<NTOT / 128, 256>>>(w0, b0);            // idx 3 -> profiled
    k_finalize<<<64, 256>>>(0, 4096, g0, be0);
    k_layer2<<<NTOT / 128, 256>>>(b1);
    k_finalize<<<64, 256>>>(1, 4096, g1, be1);
    k_layer3<<<NTOT / 64, 256>>>(b2);
    k_finalize<<<128, 256>>>(2, 8192, g2, be2);
    k_poolf<<<(BB * SS * 128) / 256, 256>>>(out);
}

// round 11
// speedup vs baseline: 1.7905x; 1.0177x over previous
#include <cuda_runtime.h>
#include <math.h>

#define BB 16
#define NN 4096
#define SS 1024
#define KK 32
#define NTOT (BB*SS*KK)   /* 524288 positions */

typedef unsigned long long ull;

// ---- packed f32x2 helpers ---------------------------------------------------
__device__ __forceinline__ ull pack2(float lo, float hi) {
    ull r; asm("mov.b64 %0, {%1, %2};" : "=l"(r) : "f"(lo), "f"(hi)); return r;
}
__device__ __forceinline__ void unpack2(ull v, float& lo, float& hi) {
    asm("mov.b64 {%0, %1}, %2;" : "=f"(lo), "=f"(hi) : "l"(v));
}
__device__ __forceinline__ ull fma2(ull a, ull b, ull c) {
    ull d; asm("fma.rn.f32x2 %0, %1, %2, %3;" : "=l"(d) : "l"(a), "l"(b), "l"(c)); return d;
}
__device__ __forceinline__ ull add2(ull a, ull b) {
    ull d; asm("add.rn.f32x2 %0, %1, %2;" : "=l"(d) : "l"(a), "l"(b)); return d;
}
__device__ __forceinline__ ull mul2(ull a, ull b) {
    ull d; asm("mul.rn.f32x2 %0, %1, %2;" : "=l"(d) : "l"(a), "l"(b)); return d;
}
__device__ __forceinline__ float warp_max_nonneg(float v) {
    unsigned r;
    asm("redux.sync.max.u32 %0, %1, 0xffffffff;" : "=r"(r) : "r"(__float_as_uint(v)));
    return __uint_as_float(r);
}

// ---------------- scratch (static device globals) ---------------------------
__device__ float d_grouped[(size_t)NTOT*6];
__device__ float d_y[(size_t)NTOT*64];
__device__ float d_mx[(size_t)BB*SS*128];
__device__ float d_mn[(size_t)BB*SS*128];
__device__ float d_ps1[64*4096],  d_pq1[64*4096];
__device__ float d_ps2[64*4096],  d_pq2[64*4096];
__device__ float d_ps3[128*8192], d_pq3[128*8192];
__device__ float d_nmean[3][128];
__device__ float d_nscale[3][128];
__device__ float d_nbeta[3][128];
__device__ ull   d_wp1[32*64];     // packed pairs: wp1[k*64+c]  = (w1[c][2k], w1[c][2k+1])
__device__ ull   d_wp2[32*128];    // packed pairs: wp2[k*128+c] = (w2[c][2k], w2[c][2k+1])

// ---------------- prep: build packed, coalesced weight-pair arrays ----------
__global__ void k_prep(const float* __restrict__ w1, const float* __restrict__ w2) {
    int t = blockIdx.x * 256 + threadIdx.x;
    if (t < 32 * 64) {
        int k = t >> 6, c = t & 63;
        d_wp1[t] = pack2(w1[c * 64 + 2 * k], w1[c * 64 + 2 * k + 1]);
    }
    if (t < 32 * 128) {
        int k = t >> 7, c = t & 127;
        d_wp2[t] = pack2(w2[c * 64 + 2 * k], w2[c * 64 + 2 * k + 1]);
    }
}

// ---------------- FPS: one block/batch; redux-based warp reduce -------------
__global__ void __launch_bounds__(256,1) k_fps(const float* __restrict__ xyz,
                                               float* __restrict__ out) {
    int b = blockIdx.x;
    int tid = threadIdx.x;
    int lane = tid & 31, wid = tid >> 5;
    const float* X = xyz + (size_t)b * NN * 3;
    __shared__ ull skey[2][8];
    ull px2[8], py2[8], pz2[8];
    float dd[16];
    int i0 = tid * 16;
    #pragma unroll
    for (int i = 0; i < 8; i++) {
        int j0 = i0 + 2*i, j1 = i0 + 2*i + 1;
        px2[i] = pack2(X[j0*3+0], X[j1*3+0]);
        py2[i] = pack2(X[j0*3+1], X[j1*3+1]);
        pz2[i] = pack2(X[j0*3+2], X[j1*3+2]);
    }
    #pragma unroll
    for (int j = 0; j < 16; j++) dd[j] = 1e10f;
    int w = 0;

    for (int it = 0; it < SS; it++) {
        float cx = __ldg(X + w * 3 + 0);
        float cy = __ldg(X + w * 3 + 1);
        float cz = __ldg(X + w * 3 + 2);
        if (tid == 0) {
            float* o = out + ((size_t)b * SS + it) * 3;
            o[0] = cx; o[1] = cy; o[2] = cz;
        }
        if (it == SS - 1) break;

        ull ncx = pack2(-cx, -cx), ncy = pack2(-cy, -cy), ncz = pack2(-cz, -cz);
        #pragma unroll
        for (int i = 0; i < 8; i++) {
            ull dx = add2(px2[i], ncx);
            ull dy = add2(py2[i], ncy);
            ull dz = add2(pz2[i], ncz);
            ull t  = mul2(dx, dx);
            t = fma2(dy, dy, t);
            t = fma2(dz, dz, t);
            float d0, d1; unpack2(t, d0, d1);
            dd[2*i]   = fminf(dd[2*i],   d0);
            dd[2*i+1] = fminf(dd[2*i+1], d1);
        }
        float m[8];
        #pragma unroll
        for (int i = 0; i < 8; i++) m[i] = fmaxf(dd[2*i], dd[2*i+1]);
        float m0 = fmaxf(fmaxf(m[0], m[1]), fmaxf(m[2], m[3]));
        float m1 = fmaxf(fmaxf(m[4], m[5]), fmaxf(m[6], m[7]));
        float bv = fmaxf(m0, m1);
        int li = 0;
        #pragma unroll
        for (int j = 15; j >= 0; j--) if (dd[j] == bv) li = i0 + j;
        float wv = warp_max_nonneg(bv);
        unsigned msk = __ballot_sync(0xffffffffu, bv == wv);
        int src = __ffs(msk) - 1;
        int wli = __shfl_sync(0xffffffffu, li, src);
        ull key = ((ull)__float_as_uint(wv) << 32) | (unsigned)(0xFFFF - wli);
        if (lane == 0) skey[it & 1][wid] = key;
        __syncthreads();
        const ull* sk = skey[it & 1];
        ull a0 = sk[0] > sk[1] ? sk[0] : sk[1];
        ull a1 = sk[2] > sk[3] ? sk[2] : sk[3];
        ull a2 = sk[4] > sk[5] ? sk[4] : sk[5];
        ull a3 = sk[6] > sk[7] ? sk[6] : sk[7];
        ull b0 = a0 > a1 ? a0 : a1;
        ull b1 = a2 > a3 ? a2 : a3;
        ull k0 = b0 > b1 ? b0 : b1;
        w = 0xFFFF - (int)(k0 & 0xFFFFFFFFull);
    }
}

// ---------------- ball query + grouping -------------------------------------
__global__ void k_group(const float* __restrict__ xyz,
                        const float* __restrict__ pts,
                        const float* __restrict__ nxyz) {
    int gw = (blockIdx.x * blockDim.x + threadIdx.x) >> 5;
    int lane = threadIdx.x & 31;
    if (gw >= BB * SS) return;
    int b = gw >> 10;
    const float* X = xyz + (size_t)b * NN * 3;
    const float* P = pts + (size_t)b * NN * 3;
    const float* c = nxyz + (size_t)gw * 3;
    float cx = c[0], cy = c[1], cz = c[2];
    float s2 = cx*cx + cy*cy + cz*cz;
    float* G = d_grouped + (size_t)gw * KK * 6;

    int count = 0, firstIdx = 0;
    bool haveFirst = false;
    for (int c4 = 0; c4 < NN / 128 && count < KK; c4++) {
        #pragma unroll
        for (int s = 0; s < 4; s++) {
            int pi = (c4 * 4 + s) * 32 + lane;
            float x = X[pi*3], y = X[pi*3+1], z = X[pi*3+2];
            float d2 = x*x + y*y + z*z;
            float dt = cx*x + cy*y + cz*z;
            float sq = (s2 + d2) - 2.0f * dt;
            bool inside = !(sq > 0.04f);
            unsigned m = __ballot_sync(0xffffffffu, inside);
            if (!haveFirst && m) { firstIdx = (c4*4+s)*32 + (__ffs(m) - 1); haveFirst = true; }
            int slot = count + __popc(m & ((1u << lane) - 1u));
            if (inside && slot < KK) {
                float* g = G + slot * 6;
                g[0] = x - cx; g[1] = y - cy; g[2] = z - cz;
                g[3] = P[pi*3]; g[4] = P[pi*3+1]; g[5] = P[pi*3+2];
            }
            count += __popc(m);
        }
    }
    if (count < KK) {
        int fi = firstIdx;
        float x = X[fi*3], y = X[fi*3+1], z = X[fi*3+2];
        float p0 = P[fi*3], p1 = P[fi*3+1], p2 = P[fi*3+2];
        for (int slot = count + lane; slot < KK; slot += 32) {
            float* g = G + slot * 6;
            g[0] = x - cx; g[1] = y - cy; g[2] = z - cz;
            g[3] = p0; g[4] = p1; g[5] = p2;
        }
    }
}

// ---------------- layer 1: 6 -> 64 ------------------------------------------
__global__ void k_layer1(const float* __restrict__ W, const float* __restrict__ Bv) {
    __shared__ __align__(16) float sin_[128 * 6];
    __shared__ float rs[256], rq[256];
    size_t pos0 = (size_t)blockIdx.x * 128;
    int tid = threadIdx.x;
    if (tid < 192) {
        float4 v = ((const float4*)(d_grouped + pos0 * 6))[tid];
        ((float4*)sin_)[tid] = v;
    }
    int c = tid & 63, g = tid >> 6;
    float w[6];
    #pragma unroll
    for (int i = 0; i < 6; i++) w[i] = W[c * 6 + i];
    float bb = Bv[c];
    __syncthreads();
    float ls = 0.f, lq = 0.f;
    for (int p = g; p < 128; p += 4) {
        float acc = bb;
        #pragma unroll
        for (int i = 0; i < 6; i++) acc += w[i] * sin_[p * 6 + i];
        d_y[(pos0 + p) * 64 + c] = acc;
        ls += acc; lq += acc * acc;
    }
    rs[tid] = ls; rq[tid] = lq;
    __syncthreads();
    if (tid < 64) {
        float S = rs[tid] + rs[tid+64] + rs[tid+128] + rs[tid+192];
        float Q = rq[tid] + rq[tid+64] + rq[tid+128] + rq[tid+192];
        d_ps1[tid * 4096 + blockIdx.x] = S;
        d_pq1[tid * 4096 + blockIdx.x] = Q;
    }
}

// ---------------- finalize --------------------------------------------------
__global__ void k_finalize(int layer, int nblk,
                           const float* __restrict__ gamma,
                           const float* __restrict__ beta) {
    const float* ps = layer == 0 ? d_ps1 : layer == 1 ? d_ps2 : d_ps3;
    const float* pq = layer == 0 ? d_pq1 : layer == 1 ? d_pq2 : d_pq3;
    int c = blockIdx.x;
    __shared__ double sd[256], sq[256];
    double s = 0.0, q = 0.0;
    const float4* ps4 = (const float4*)(ps + (size_t)c * nblk);
    const float4* pq4 = (const float4*)(pq + (size_t)c * nblk);
    for (int i = threadIdx.x; i < nblk / 4; i += 256) {
        float4 a = ps4[i], bq = pq4[i];
        s += (double)a.x + a.y + a.z + a.w;
        q += (double)bq.x + bq.y + bq.z + bq.w;
    }
    sd[threadIdx.x] = s; sq[threadIdx.x] = q;
    __syncthreads();
    for (int off = 128; off; off >>= 1) {
        if (threadIdx.x < off) {
            sd[threadIdx.x] += sd[threadIdx.x + off];
            sq[threadIdx.x] += sq[threadIdx.x + off];
        }
        __syncthreads();
    }
    if (threadIdx.x == 0) {
        double n = (double)NTOT;
        double mean = sd[0] / n;
        double var  = sq[0] / n - mean * mean;
        float rstd = rsqrtf((float)var + 1e-5f);
        d_nmean[layer][c]  = (float)mean;
        d_nscale[layer][c] = gamma[c] * rstd;
        d_nbeta[layer][c]  = beta[c];
    }
}

// ---------------- layer 2: 64 -> 64, channel-pair FFMA2, 2 blocks/SM --------
__global__ void __launch_bounds__(256,2) k_layer2(const float* __restrict__ Bv) {
    __shared__ __align__(16) float s[128 * 64];   // position-major, natural
    __shared__ float rs[256], rq[256];
    size_t pos0 = (size_t)blockIdx.x * 128;
    int tid = threadIdx.x;
    {
        int cin0 = (tid & 15) * 4;
        float nm0 = d_nmean[0][cin0],   sc0 = d_nscale[0][cin0],   nb0 = d_nbeta[0][cin0];
        float nm1 = d_nmean[0][cin0+1], sc1 = d_nscale[0][cin0+1], nb1 = d_nbeta[0][cin0+1];
        float nm2 = d_nmean[0][cin0+2], sc2 = d_nscale[0][cin0+2], nb2 = d_nbeta[0][cin0+2];
        float nm3 = d_nmean[0][cin0+3], sc3 = d_nscale[0][cin0+3], nb3 = d_nbeta[0][cin0+3];
        const float4* src = (const float4*)(d_y + pos0 * 64);
        float4* dst = (float4*)s;
        for (int t4 = tid; t4 < 2048; t4 += 256) {
            float4 v = src[t4];
            v.x = fmaxf((v.x - nm0) * sc0 + nb0, 0.f);
            v.y = fmaxf((v.y - nm1) * sc1 + nb1, 0.f);
            v.z = fmaxf((v.z - nm2) * sc2 + nb2, 0.f);
            v.w = fmaxf((v.w - nm3) * sc3 + nb3, 0.f);
            dst[t4] = v;
        }
    }
    int c = tid & 63, g = tid >> 6;
    ull wr[32];
    #pragma unroll
    for (int k = 0; k < 32; k++) wr[k] = d_wp1[k * 64 + c];
    float bb = Bv[c];
    __syncthreads();
    float ls = 0.f, lq = 0.f;
    for (int p = g; p < 128; p += 4) {
        const ulonglong2* sp = (const ulonglong2*)(s + p * 64);
        ull acc_a = pack2(bb, 0.f), acc_b = pack2(0.f, 0.f);
        #pragma unroll
        for (int j = 0; j < 16; j++) {
            ulonglong2 v = sp[j];
            acc_a = fma2(wr[2*j],   v.x, acc_a);
            acc_b = fma2(wr[2*j+1], v.y, acc_b);
        }
        ull acc = add2(acc_a, acc_b);
        float lo, hi; unpack2(acc, lo, hi);
        float r = lo + hi;
        d_y[(pos0 + p) * 64 + c] = r;
        ls += r; lq += r * r;
    }
    rs[tid] = ls; rq[tid] = lq;
    __syncthreads();
    if (tid < 64) {
        float S = rs[tid] + rs[tid+64] + rs[tid+128] + rs[tid+192];
        float Q = rq[tid] + rq[tid+64] + rq[tid+128] + rq[tid+192];
        d_ps2[tid * 4096 + blockIdx.x] = S;
        d_pq2[tid * 4096 + blockIdx.x] = Q;
    }
}

// ---------------- layer 3: 64 -> 128, channel-pair FFMA2, fused pool --------
__global__ void __launch_bounds__(256,2) k_layer3(const float* __restrict__ Bv) {
    __shared__ __align__(16) float s[64 * 64];    // 16KB
    __shared__ float rs[256], rq[256];
    __shared__ float smx[2][2][128], smn[2][2][128];
    size_t pos0 = (size_t)blockIdx.x * 64;        // 2 centroids per block
    int tid = threadIdx.x;
    {
        int cin0 = (tid & 15) * 4;
        float nm0 = d_nmean[1][cin0],   sc0 = d_nscale[1][cin0],   nb0 = d_nbeta[1][cin0];
        float nm1 = d_nmean[1][cin0+1], sc1 = d_nscale[1][cin0+1], nb1 = d_nbeta[1][cin0+1];
        float nm2 = d_nmean[1][cin0+2], sc2 = d_nscale[1][cin0+2], nb2 = d_nbeta[1][cin0+2];
        float nm3 = d_nmean[1][cin0+3], sc3 = d_nscale[1][cin0+3], nb3 = d_nbeta[1][cin0+3];
        const float4* src = (const float4*)(d_y + pos0 * 64);
        float4* dst = (float4*)s;
        for (int t4 = tid; t4 < 1024; t4 += 256) {
            float4 v = src[t4];
            v.x = fmaxf((v.x - nm0) * sc0 + nb0, 0.f);
            v.y = fmaxf((v.y - nm1) * sc1 + nb1, 0.f);
            v.z = fmaxf((v.z - nm2) * sc2 + nb2, 0.f);
            v.w = fmaxf((v.w - nm3) * sc3 + nb3, 0.f);
            dst[t4] = v;
        }
    }
    int c = tid & 127, g = tid >> 7;
    ull wr[32];
    #pragma unroll
    for (int k = 0; k < 32; k++) wr[k] = d_wp2[k * 128 + c];
    float bb = Bv[c];
    __syncthreads();
    float ls = 0.f, lq = 0.f;
    float mx0 = -INFINITY, mn0 = INFINITY, mx1 = -INFINITY, mn1 = INFINITY;
    for (int p = g; p < 64; p += 2) {
        const ulonglong2* sp = (const ulonglong2*)(s + p * 64);
        ull acc_a = pack2(bb, 0.f), acc_b = pack2(0.f, 0.f);
        #pragma unroll
        for (int j = 0; j < 16; j++) {
            ulonglong2 v = sp[j];
            acc_a = fma2(wr[2*j],   v.x, acc_a);
            acc_b = fma2(wr[2*j+1], v.y, acc_b);
        }
        ull acc = add2(acc_a, acc_b);
        float lo, hi; unpack2(acc, lo, hi);
        float r = lo + hi;
        ls += r; lq += r * r;
        if (p < 32) { mx0 = fmaxf(mx0, r); mn0 = fminf(mn0, r); }
        else        { mx1 = fmaxf(mx1, r); mn1 = fminf(mn1, r); }
    }
    smx[g][0][c] = mx0; smx[g][1][c] = mx1;
    smn[g][0][c] = mn0; smn[g][1][c] = mn1;
    rs[tid] = ls; rq[tid] = lq;
    __syncthreads();
    {
        int cent = tid >> 7, cc = tid & 127;
        float M = fmaxf(smx[0][cent][cc], smx[1][cent][cc]);
        float m = fminf(smn[0][cent][cc], smn[1][cent][cc]);
        size_t o = (size_t)(blockIdx.x * 2 + cent) * 128 + cc;
        d_mx[o] = M; d_mn[o] = m;
    }
    if (tid < 128) {
        float S = rs[tid] + rs[tid + 128];
        float Q = rq[tid] + rq[tid + 128];
        d_ps3[tid * 8192 + blockIdx.x] = S;
        d_pq3[tid * 8192 + blockIdx.x] = Q;
    }
}

// ---------------- final pool -------------------------------------------------
__global__ void k_poolf(float* __restrict__ out) {
    int g = blockIdx.x * 256 + threadIdx.x;
    int c = g & 127;
    float scv = d_nscale[2][c];
    float v = (scv >= 0.f) ? d_mx[g] : d_mn[g];
    out[(size_t)BB * SS * 3 + g] = fmaxf((v - d_nmean[2][c]) * scv + d_nbeta[2][c], 0.f);
}

// ---------------- launch -----------------------------------------------------
extern "C" void kernel_launch(void* const* d_in, const int* in_sizes, int n_in,
                              void* d_out, int out_size) {
    const float* xyz = (const float*)d_in[0];
    const float* pts = (const float*)d_in[1];
    const float* w0  = (const float*)d_in[2];
    const float* b0  = (const float*)d_in[3];
    const float* g0  = (const float*)d_in[4];
    const float* be0 = (const float*)d_in[5];
    const float* w1  = (const float*)d_in[6];
    const float* b1  = (const float*)d_in[7];
    const float* g1  = (const float*)d_in[8];
    const float* be1 = (const float*)d_in[9];
    const float* w2  = (const float*)d_in[10];
    const float* b2  = (const float*)d_in[11];
    const float* g2  = (const float*)d_in[12];
    const float* be2 = (const float*)d_in[13];
    float* out = (float*)d_out;

    k_prep<<<32, 256>>>(w1, w2);                      // idx 0
    k_fps<<<BB, 256>>>(xyz, out);                     // idx 1
    k_group<<<(BB * SS) / 8, 256>>>(xyz, pts, out);   // idx 2
    k_layer1<<<NTOT / 128, 256>>>(w0, b0);            // idx 3 -> profiled
    k_finalize<<<64, 256>>>(0, 4096, g0, be0);
    k_layer2<<<NTOT / 128, 256>>>(b1);
    k_finalize<<<64, 256>>>(1, 4096, g1, be1);
    k_layer3<<<NTOT / 64, 256>>>(b2);
    k_finalize<<<128, 256>>>(2, 8192, g2, be2);
    k_poolf<<<(BB * SS * 128) / 256, 256>>>(out);
}

// round 12
// speedup vs baseline: 1.8436x; 1.0296x over previous
#include <cuda_runtime.h>
#include <math.h>

#define BB 16
#define NN 4096
#define SS 1024
#define KK 32
#define NTOT (BB*SS*KK)   /* 524288 positions */

typedef unsigned long long ull;

// ---- packed f32x2 helpers ---------------------------------------------------
__device__ __forceinline__ ull pack2(float lo, float hi) {
    ull r; asm("mov.b64 %0, {%1, %2};" : "=l"(r) : "f"(lo), "f"(hi)); return r;
}
__device__ __forceinline__ void unpack2(ull v, float& lo, float& hi) {
    asm("mov.b64 {%0, %1}, %2;" : "=f"(lo), "=f"(hi) : "l"(v));
}
__device__ __forceinline__ ull fma2(ull a, ull b, ull c) {
    ull d; asm("fma.rn.f32x2 %0, %1, %2, %3;" : "=l"(d) : "l"(a), "l"(b), "l"(c)); return d;
}
__device__ __forceinline__ ull add2(ull a, ull b) {
    ull d; asm("add.rn.f32x2 %0, %1, %2;" : "=l"(d) : "l"(a), "l"(b)); return d;
}
__device__ __forceinline__ ull mul2(ull a, ull b) {
    ull d; asm("mul.rn.f32x2 %0, %1, %2;" : "=l"(d) : "l"(a), "l"(b)); return d;
}
__device__ __forceinline__ float warp_max_nonneg(float v) {
    unsigned r;
    asm("redux.sync.max.u32 %0, %1, 0xffffffff;" : "=r"(r) : "r"(__float_as_uint(v)));
    return __uint_as_float(r);
}

// ---------------- scratch (static device globals) ---------------------------
__device__ float d_y[(size_t)NTOT*64];
__device__ float d_mx[(size_t)BB*SS*128];
__device__ float d_mn[(size_t)BB*SS*128];
__device__ float d_ps1[64*4096],  d_pq1[64*4096];
__device__ float d_ps2[64*4096],  d_pq2[64*4096];
__device__ float d_ps3[128*8192], d_pq3[128*8192];
__device__ float d_nmean[3][128];
__device__ float d_nscale[3][128];
__device__ float d_nbeta[3][128];
__device__ ull   d_wp1[32*64];     // (w1[c][2k], w1[c][2k+1]) at [k*64+c]
__device__ ull   d_wp2[32*128];    // (w2[c][2k], w2[c][2k+1]) at [k*128+c]

// ---------------- FPS: one block/batch; redux-based warp reduce -------------
__global__ void __launch_bounds__(256,1) k_fps(const float* __restrict__ xyz,
                                               float* __restrict__ out) {
    int b = blockIdx.x;
    int tid = threadIdx.x;
    int lane = tid & 31, wid = tid >> 5;
    const float* X = xyz + (size_t)b * NN * 3;
    __shared__ ull skey[2][8];
    ull px2[8], py2[8], pz2[8];
    float dd[16];
    int i0 = tid * 16;
    #pragma unroll
    for (int i = 0; i < 8; i++) {
        int j0 = i0 + 2*i, j1 = i0 + 2*i + 1;
        px2[i] = pack2(X[j0*3+0], X[j1*3+0]);
        py2[i] = pack2(X[j0*3+1], X[j1*3+1]);
        pz2[i] = pack2(X[j0*3+2], X[j1*3+2]);
    }
    #pragma unroll
    for (int j = 0; j < 16; j++) dd[j] = 1e10f;
    int w = 0;

    for (int it = 0; it < SS; it++) {
        float cx = __ldg(X + w * 3 + 0);
        float cy = __ldg(X + w * 3 + 1);
        float cz = __ldg(X + w * 3 + 2);
        if (tid == 0) {
            float* o = out + ((size_t)b * SS + it) * 3;
            o[0] = cx; o[1] = cy; o[2] = cz;
        }
        if (it == SS - 1) break;

        ull ncx = pack2(-cx, -cx), ncy = pack2(-cy, -cy), ncz = pack2(-cz, -cz);
        #pragma unroll
        for (int i = 0; i < 8; i++) {
            ull dx = add2(px2[i], ncx);
            ull dy = add2(py2[i], ncy);
            ull dz = add2(pz2[i], ncz);
            ull t  = mul2(dx, dx);
            t = fma2(dy, dy, t);
            t = fma2(dz, dz, t);
            float d0, d1; unpack2(t, d0, d1);
            dd[2*i]   = fminf(dd[2*i],   d0);
            dd[2*i+1] = fminf(dd[2*i+1], d1);
        }
        float m[8];
        #pragma unroll
        for (int i = 0; i < 8; i++) m[i] = fmaxf(dd[2*i], dd[2*i+1]);
        float m0 = fmaxf(fmaxf(m[0], m[1]), fmaxf(m[2], m[3]));
        float m1 = fmaxf(fmaxf(m[4], m[5]), fmaxf(m[6], m[7]));
        float bv = fmaxf(m0, m1);
        int li = 0;
        #pragma unroll
        for (int j = 15; j >= 0; j--) if (dd[j] == bv) li = i0 + j;
        float wv = warp_max_nonneg(bv);
        unsigned msk = __ballot_sync(0xffffffffu, bv == wv);
        int src = __ffs(msk) - 1;
        int wli = __shfl_sync(0xffffffffu, li, src);
        ull key = ((ull)__float_as_uint(wv) << 32) | (unsigned)(0xFFFF - wli);
        if (lane == 0) skey[it & 1][wid] = key;
        __syncthreads();
        const ull* sk = skey[it & 1];
        ull a0 = sk[0] > sk[1] ? sk[0] : sk[1];
        ull a1 = sk[2] > sk[3] ? sk[2] : sk[3];
        ull a2 = sk[4] > sk[5] ? sk[4] : sk[5];
        ull a3 = sk[6] > sk[7] ? sk[6] : sk[7];
        ull b0 = a0 > a1 ? a0 : a1;
        ull b1 = a2 > a3 ? a2 : a3;
        ull k0 = b0 > b1 ? b0 : b1;
        w = 0xFFFF - (int)(k0 & 0xFFFFFFFFull);
    }
}

// ---------------- fused ball-query + grouping + layer1 (6->64) --------------
// One warp per centroid: scan points, stage up to 32 member features in smem,
// then convolve 6->64 directly (lane owns 2 output channels) and write d_y +
// per-block stats. d_grouped round-trip eliminated. FFMA order matches the
// old k_layer1 exactly -> d_y bit-identical.
__global__ void __launch_bounds__(256,4) k_gconv(const float* __restrict__ xyz,
                                                 const float* __restrict__ pts,
                                                 const float* __restrict__ nxyz,
                                                 const float* __restrict__ W0,
                                                 const float* __restrict__ B0,
                                                 const float* __restrict__ w1,
                                                 const float* __restrict__ w2) {
    __shared__ __align__(16) float feat[8][32][8];   // 8KB (6 used, pad to 8)
    __shared__ float rs[8][64], rq[8][64];           // 4KB
    int tid = threadIdx.x;
    int wid = tid >> 5, lane = tid & 31;

    // block 0 also packs the l2/l3 weight-pair arrays (replaces k_prep)
    if (blockIdx.x == 0) {
        for (int t = tid; t < 32 * 64; t += 256) {
            int k = t >> 6, c = t & 63;
            d_wp1[t] = pack2(w1[c * 64 + 2 * k], w1[c * 64 + 2 * k + 1]);
        }
        for (int t = tid; t < 32 * 128; t += 256) {
            int k = t >> 7, c = t & 127;
            d_wp2[t] = pack2(w2[c * 64 + 2 * k], w2[c * 64 + 2 * k + 1]);
        }
    }

    int gw = blockIdx.x * 8 + wid;                   // centroid id
    int b = gw >> 10;
    const float* X = xyz + (size_t)b * NN * 3;
    const float* P = pts + (size_t)b * NN * 3;
    const float* cc = nxyz + (size_t)gw * 3;
    float cx = cc[0], cy = cc[1], cz = cc[2];
    float s2 = cx*cx + cy*cy + cz*cz;

    int count = 0;
    for (int c4 = 0; c4 < NN / 128 && count < KK; c4++) {
        #pragma unroll
        for (int s = 0; s < 4; s++) {
            int pi = (c4 * 4 + s) * 32 + lane;
            float x = X[pi*3], y = X[pi*3+1], z = X[pi*3+2];
            float d2 = x*x + y*y + z*z;
            float dt = cx*x + cy*y + cz*z;
            float sq = (s2 + d2) - 2.0f * dt;
            bool inside = !(sq > 0.04f);
            unsigned m = __ballot_sync(0xffffffffu, inside);
            int slot = count + __popc(m & ((1u << lane) - 1u));
            if (inside && slot < KK) {
                float* f = feat[wid][slot];
                f[0] = x - cx; f[1] = y - cy; f[2] = z - cz;
                f[3] = P[pi*3]; f[4] = P[pi*3+1]; f[5] = P[pi*3+2];
            }
            count += __popc(m);
        }
    }
    __syncwarp();
    if (count < KK && lane >= count) {               // pad = first member (slot 0)
        float* f = feat[wid][lane];
        const float* f0 = feat[wid][0];
        #pragma unroll
        for (int i = 0; i < 6; i++) f[i] = f0[i];
    }
    __syncwarp();

    // conv 6->64: lane owns channels 2*lane, 2*lane+1
    int c0 = lane * 2;
    float wA[6], wB[6];
    #pragma unroll
    for (int i = 0; i < 6; i++) { wA[i] = W0[c0 * 6 + i]; wB[i] = W0[(c0 + 1) * 6 + i]; }
    float bbA = B0[c0], bbB = B0[c0 + 1];
    float ls0 = 0.f, lq0 = 0.f, ls1 = 0.f, lq1 = 0.f;
    float2* Y = (float2*)(d_y + (size_t)gw * 32 * 64);
    #pragma unroll 4
    for (int s = 0; s < 32; s++) {
        float4 fa = *(const float4*)feat[wid][s];        // broadcast LDS.128
        float2 fb = *(const float2*)(feat[wid][s] + 4);  // broadcast LDS.64
        float aA = bbA, aB = bbB;
        aA += wA[0]*fa.x; aB += wB[0]*fa.x;
        aA += wA[1]*fa.y; aB += wB[1]*fa.y;
        aA += wA[2]*fa.z; aB += wB[2]*fa.z;
        aA += wA[3]*fa.w; aB += wB[3]*fa.w;
        aA += wA[4]*fb.x; aB += wB[4]*fb.x;
        aA += wA[5]*fb.y; aB += wB[5]*fb.y;
        Y[s * 32 + lane] = make_float2(aA, aB);
        ls0 += aA; lq0 += aA*aA; ls1 += aB; lq1 += aB*aB;
    }
    rs[wid][c0] = ls0; rs[wid][c0+1] = ls1;
    rq[wid][c0] = lq0; rq[wid][c0+1] = lq1;
    __syncthreads();
    if (tid < 64) {
        float S = 0.f, Q = 0.f;
        #pragma unroll
        for (int ww = 0; ww < 8; ww++) { S += rs[ww][tid]; Q += rq[ww][tid]; }
        d_ps1[tid * 2048 + blockIdx.x] = S;
        d_pq1[tid * 2048 + blockIdx.x] = Q;
    }
}

// ---------------- finalize --------------------------------------------------
__global__ void k_finalize(int layer, int nblk,
                           const float* __restrict__ gamma,
                           const float* __restrict__ beta) {
    const float* ps = layer == 0 ? d_ps1 : layer == 1 ? d_ps2 : d_ps3;
    const float* pq = layer == 0 ? d_pq1 : layer == 1 ? d_pq2 : d_pq3;
    int c = blockIdx.x;
    __shared__ double sd[256], sq[256];
    double s = 0.0, q = 0.0;
    const float4* ps4 = (const float4*)(ps + (size_t)c * nblk);
    const float4* pq4 = (const float4*)(pq + (size_t)c * nblk);
    for (int i = threadIdx.x; i < nblk / 4; i += 256) {
        float4 a = ps4[i], bq = pq4[i];
        s += (double)a.x + a.y + a.z + a.w;
        q += (double)bq.x + bq.y + bq.z + bq.w;
    }
    sd[threadIdx.x] = s; sq[threadIdx.x] = q;
    __syncthreads();
    for (int off = 128; off; off >>= 1) {
        if (threadIdx.x < off) {
            sd[threadIdx.x] += sd[threadIdx.x + off];
            sq[threadIdx.x] += sq[threadIdx.x + off];
        }
        __syncthreads();
    }
    if (threadIdx.x == 0) {
        double n = (double)NTOT;
        double mean = sd[0] / n;
        double var  = sq[0] / n - mean * mean;
        float rstd = rsqrtf((float)var + 1e-5f);
        d_nmean[layer][c]  = (float)mean;
        d_nscale[layer][c] = gamma[c] * rstd;
        d_nbeta[layer][c]  = beta[c];
    }
}

// ---------------- layer 2: 64 -> 64 (profiled this round) -------------------
__global__ void __launch_bounds__(256,2) k_layer2(const float* __restrict__ Bv) {
    __shared__ __align__(16) float s[128 * 64];
    __shared__ float rs[256], rq[256];
    size_t pos0 = (size_t)blockIdx.x * 128;
    int tid = threadIdx.x;
    {
        int cin0 = (tid & 15) * 4;
        float nm0 = d_nmean[0][cin0],   sc0 = d_nscale[0][cin0],   nb0 = d_nbeta[0][cin0];
        float nm1 = d_nmean[0][cin0+1], sc1 = d_nscale[0][cin0+1], nb1 = d_nbeta[0][cin0+1];
        float nm2 = d_nmean[0][cin0+2], sc2 = d_nscale[0][cin0+2], nb2 = d_nbeta[0][cin0+2];
        float nm3 = d_nmean[0][cin0+3], sc3 = d_nscale[0][cin0+3], nb3 = d_nbeta[0][cin0+3];
        const float4* src = (const float4*)(d_y + pos0 * 64);
        float4* dst = (float4*)s;
        for (int t4 = tid; t4 < 2048; t4 += 256) {
            float4 v = src[t4];
            v.x = fmaxf((v.x - nm0) * sc0 + nb0, 0.f);
            v.y = fmaxf((v.y - nm1) * sc1 + nb1, 0.f);
            v.z = fmaxf((v.z - nm2) * sc2 + nb2, 0.f);
            v.w = fmaxf((v.w - nm3) * sc3 + nb3, 0.f);
            dst[t4] = v;
        }
    }
    int c = tid & 63, g = tid >> 6;
    ull wr[32];
    #pragma unroll
    for (int k = 0; k < 32; k++) wr[k] = d_wp1[k * 64 + c];
    float bb = Bv[c];
    __syncthreads();
    float ls = 0.f, lq = 0.f;
    for (int p = g; p < 128; p += 4) {
        const ulonglong2* sp = (const ulonglong2*)(s + p * 64);
        ull acc_a = pack2(bb, 0.f), acc_b = pack2(0.f, 0.f);
        #pragma unroll
        for (int j = 0; j < 16; j++) {
            ulonglong2 v = sp[j];
            acc_a = fma2(wr[2*j],   v.x, acc_a);
            acc_b = fma2(wr[2*j+1], v.y, acc_b);
        }
        ull acc = add2(acc_a, acc_b);
        float lo, hi; unpack2(acc, lo, hi);
        float r = lo + hi;
        d_y[(pos0 + p) * 64 + c] = r;
        ls += r; lq += r * r;
    }
    rs[tid] = ls; rq[tid] = lq;
    __syncthreads();
    if (tid < 64) {
        float S = rs[tid] + rs[tid+64] + rs[tid+128] + rs[tid+192];
        float Q = rq[tid] + rq[tid+64] + rq[tid+128] + rq[tid+192];
        d_ps2[tid * 4096 + blockIdx.x] = S;
        d_pq2[tid * 4096 + blockIdx.x] = Q;
    }
}

// ---------------- layer 3: 64 -> 128, fused max/min pool --------------------
__global__ void __launch_bounds__(256,2) k_layer3(const float* __restrict__ Bv) {
    __shared__ __align__(16) float s[64 * 64];
    __shared__ float rs[256], rq[256];
    __shared__ float smx[2][2][128], smn[2][2][128];
    size_t pos0 = (size_t)blockIdx.x * 64;
    int tid = threadIdx.x;
    {
        int cin0 = (tid & 15) * 4;
        float nm0 = d_nmean[1][cin0],   sc0 = d_nscale[1][cin0],   nb0 = d_nbeta[1][cin0];
        float nm1 = d_nmean[1][cin0+1], sc1 = d_nscale[1][cin0+1], nb1 = d_nbeta[1][cin0+1];
        float nm2 = d_nmean[1][cin0+2], sc2 = d_nscale[1][cin0+2], nb2 = d_nbeta[1][cin0+2];
        float nm3 = d_nmean[1][cin0+3], sc3 = d_nscale[1][cin0+3], nb3 = d_nbeta[1][cin0+3];
        const float4* src = (const float4*)(d_y + pos0 * 64);
        float4* dst = (float4*)s;
        for (int t4 = tid; t4 < 1024; t4 += 256) {
            float4 v = src[t4];
            v.x = fmaxf((v.x - nm0) * sc0 + nb0, 0.f);
            v.y = fmaxf((v.y - nm1) * sc1 + nb1, 0.f);
            v.z = fmaxf((v.z - nm2) * sc2 + nb2, 0.f);
            v.w = fmaxf((v.w - nm3) * sc3 + nb3, 0.f);
            dst[t4] = v;
        }
    }
    int c = tid & 127, g = tid >> 7;
    ull wr[32];
    #pragma unroll
    for (int k = 0; k < 32; k++) wr[k] = d_wp2[k * 128 + c];
    float bb = Bv[c];
    __syncthreads();
    float ls = 0.f, lq = 0.f;
    float mx0 = -INFINITY, mn0 = INFINITY, mx1 = -INFINITY, mn1 = INFINITY;
    for (int p = g; p < 64; p += 2) {
        const ulonglong2* sp = (const ulonglong2*)(s + p * 64);
        ull acc_a = pack2(bb, 0.f), acc_b = pack2(0.f, 0.f);
        #pragma unroll
        for (int j = 0; j < 16; j++) {
            ulonglong2 v = sp[j];
            acc_a = fma2(wr[2*j],   v.x, acc_a);
            acc_b = fma2(wr[2*j+1], v.y, acc_b);
        }
        ull acc = add2(acc_a, acc_b);
        float lo, hi; unpack2(acc, lo, hi);
        float r = lo + hi;
        ls += r; lq += r * r;
        if (p < 32) { mx0 = fmaxf(mx0, r); mn0 = fminf(mn0, r); }
        else        { mx1 = fmaxf(mx1, r); mn1 = fminf(mn1, r); }
    }
    smx[g][0][c] = mx0; smx[g][1][c] = mx1;
    smn[g][0][c] = mn0; smn[g][1][c] = mn1;
    rs[tid] = ls; rq[tid] = lq;
    __syncthreads();
    {
        int cent = tid >> 7, ccq = tid & 127;
        float M = fmaxf(smx[0][cent][ccq], smx[1][cent][ccq]);
        float m = fminf(smn[0][cent][ccq], smn[1][cent][ccq]);
        size_t o = (size_t)(blockIdx.x * 2 + cent) * 128 + ccq;
        d_mx[o] = M; d_mn[o] = m;
    }
    if (tid < 128) {
        float S = rs[tid] + rs[tid + 128];
        float Q = rq[tid] + rq[tid + 128];
        d_ps3[tid * 8192 + blockIdx.x] = S;
        d_pq3[tid * 8192 + blockIdx.x] = Q;
    }
}

// ---------------- final pool -------------------------------------------------
__global__ void k_poolf(float* __restrict__ out) {
    int g = blockIdx.x * 256 + threadIdx.x;
    int c = g & 127;
    float scv = d_nscale[2][c];
    float v = (scv >= 0.f) ? d_mx[g] : d_mn[g];
    out[(size_t)BB * SS * 3 + g] = fmaxf((v - d_nmean[2][c]) * scv + d_nbeta[2][c], 0.f);
}

// ---------------- launch -----------------------------------------------------
extern "C" void kernel_launch(void* const* d_in, const int* in_sizes, int n_in,
                              void* d_out, int out_size) {
    const float* xyz = (const float*)d_in[0];
    const float* pts = (const float*)d_in[1];
    const float* w0  = (const float*)d_in[2];
    const float* b0  = (const float*)d_in[3];
    const float* g0  = (const float*)d_in[4];
    const float* be0 = (const float*)d_in[5];
    const float* w1  = (const float*)d_in[6];
    const float* b1  = (const float*)d_in[7];
    const float* g1  = (const float*)d_in[8];
    const float* be1 = (const float*)d_in[9];
    const float* w2  = (const float*)d_in[10];
    const float* b2  = (const float*)d_in[11];
    const float* g2  = (const float*)d_in[12];
    const float* be2 = (const float*)d_in[13];
    float* out = (float*)d_out;

    k_fps<<<BB, 256>>>(xyz, out);                               // idx 0
    k_gconv<<<(BB * SS) / 8, 256>>>(xyz, pts, out, w0, b0, w1, w2); // idx 1
    k_finalize<<<64, 256>>>(0, 2048, g0, be0);                  // idx 2
    k_layer2<<<NTOT / 128, 256>>>(b1);                          // idx 3 -> profiled
    k_finalize<<<64, 256>>>(1, 4096, g1, be1);
    k_layer3<<<NTOT / 64, 256>>>(b2);
    k_finalize<<<128, 256>>>(2, 8192, g2, be2);
    k_poolf<<<(BB * SS * 128) / 256, 256>>>(out);
}